// round 2
// baseline (speedup 1.0000x reference)
#include <cuda_runtime.h>
#include <cuda_bf16.h>

// Problem constants (fixed by the dataset)
#define NN      100000
#define FIN     128
#define HEADS   2
#define CDIM    64
#define FOUT    128          // HEADS*CDIM
#define EE      1600000
#define NEG_SLOPE 0.2f

#define NB_SCAN ((NN + 1023) / 1024)   // 98

// ---------------- scratch (static device globals; no allocation) ------------
__device__ float g_hlin[NN * FOUT];    // post-GEMM features (gather source)
__device__ float g_hpost[NN * FOUT];   // layer output after bias+ELU
__device__ float g_as[NN * HEADS];
__device__ float g_ad[NN * HEADS];
__device__ int   g_deg[NN];
__device__ int   g_cursor[NN];
__device__ int   g_rowptr[NN + 1];
__device__ int   g_csrc[EE];
__device__ int   g_bsum[128];
__device__ int   g_bscan[128];

__device__ __forceinline__ float leaky(float e) {
    return fmaxf(e, NEG_SLOPE * e);
}
__device__ __forceinline__ float elu(float x) {
    return x > 0.f ? x : (__expf(x) - 1.f);
}

// ---------------- CSR build -------------------------------------------------
__global__ void init_kernel(int n) {
    int i = blockIdx.x * blockDim.x + threadIdx.x;
    if (i < n) { g_deg[i] = 0; g_cursor[i] = 0; }
}

__global__ void count_kernel(const int* __restrict__ dst, int e) {
    int i = blockIdx.x * blockDim.x + threadIdx.x;
    if (i < e) atomicAdd(&g_deg[dst[i]], 1);
}

__global__ void scan_local_kernel(int n) {
    __shared__ int sm[1024];
    int i = blockIdx.x * 1024 + threadIdx.x;
    int v = (i < n) ? g_deg[i] : 0;
    sm[threadIdx.x] = v;
    __syncthreads();
    #pragma unroll
    for (int off = 1; off < 1024; off <<= 1) {
        int t = (threadIdx.x >= off) ? sm[threadIdx.x - off] : 0;
        __syncthreads();
        sm[threadIdx.x] += t;
        __syncthreads();
    }
    if (i < n) g_rowptr[i] = sm[threadIdx.x] - v;   // block-exclusive
    if (threadIdx.x == 1023) g_bsum[blockIdx.x] = sm[1023];
}

__global__ void scan_bsums_kernel(int nb, int n) {
    __shared__ int sm[128];
    int v = (threadIdx.x < nb) ? g_bsum[threadIdx.x] : 0;
    sm[threadIdx.x] = v;
    __syncthreads();
    #pragma unroll
    for (int off = 1; off < 128; off <<= 1) {
        int t = (threadIdx.x >= off) ? sm[threadIdx.x - off] : 0;
        __syncthreads();
        sm[threadIdx.x] += t;
        __syncthreads();
    }
    g_bscan[threadIdx.x] = sm[threadIdx.x] - v;     // exclusive
    if (threadIdx.x == 127) g_rowptr[n] = sm[127];  // total
}

__global__ void add_offsets_kernel(int n) {
    int i = blockIdx.x * 1024 + threadIdx.x;
    if (i < n) g_rowptr[i] += g_bscan[blockIdx.x];
}

__global__ void fill_kernel(const int* __restrict__ src, const int* __restrict__ dst, int e) {
    int i = blockIdx.x * blockDim.x + threadIdx.x;
    if (i < e) {
        int d = dst[i];
        int pos = g_rowptr[d] + atomicAdd(&g_cursor[d], 1);
        g_csrc[pos] = src[i];
    }
}

// ---------------- GEMM: [n,128] @ [128,128] -> g_hlin -----------------------
// BM=64, BN=128, BK=16, 256 threads, 4x8 microtile
template <bool FIRST>
__global__ void gemm_kernel(const float* __restrict__ xext,
                            const float* __restrict__ W, int n) {
    __shared__ float As[64][17];
    __shared__ float Bs[16][128];
    const float* A = FIRST ? xext : g_hpost;
    int tid = threadIdx.x;
    int tx = tid & 15, ty = tid >> 4;
    int row0 = blockIdx.x * 64;
    float acc[4][8];
    #pragma unroll
    for (int i = 0; i < 4; i++)
        #pragma unroll
        for (int j = 0; j < 8; j++) acc[i][j] = 0.f;

    for (int k0 = 0; k0 < 128; k0 += 16) {
        {
            int r = tid >> 2, c = (tid & 3) << 2;
            int gr = row0 + r;
            float4 v = make_float4(0.f, 0.f, 0.f, 0.f);
            if (gr < n) v = *(const float4*)&A[gr * 128 + k0 + c];
            As[r][c] = v.x; As[r][c + 1] = v.y; As[r][c + 2] = v.z; As[r][c + 3] = v.w;
        }
        #pragma unroll
        for (int l = 0; l < 2; l++) {
            int e = tid + l * 256;
            int kr = e >> 5, kc = (e & 31) << 2;
            *(float4*)&Bs[kr][kc] = *(const float4*)&W[(k0 + kr) * 128 + kc];
        }
        __syncthreads();
        #pragma unroll
        for (int kk = 0; kk < 16; kk++) {
            float a[4], b[8];
            #pragma unroll
            for (int i = 0; i < 4; i++) a[i] = As[ty * 4 + i][kk];
            #pragma unroll
            for (int j = 0; j < 8; j++) b[j] = Bs[kk][tx + j * 16];
            #pragma unroll
            for (int i = 0; i < 4; i++)
                #pragma unroll
                for (int j = 0; j < 8; j++) acc[i][j] += a[i] * b[j];
        }
        __syncthreads();
    }
    #pragma unroll
    for (int i = 0; i < 4; i++) {
        int gr = row0 + ty * 4 + i;
        if (gr < n) {
            #pragma unroll
            for (int j = 0; j < 8; j++)
                g_hlin[gr * 128 + tx + j * 16] = acc[i][j];
        }
    }
}

// ---------------- per-node attention logits ---------------------------------
// one warp per node: alpha_s[n,h] = <h[n,h,:], a_src[h,:]>
__global__ void alpha_kernel(const float* __restrict__ a_src,
                             const float* __restrict__ a_dst, int n) {
    int w = (blockIdx.x * blockDim.x + threadIdx.x) >> 5;
    int lane = threadIdx.x & 31;
    if (w >= n) return;
    int f = lane * 4;
    float4 hv = *(const float4*)&g_hlin[w * 128 + f];
    float4 s4 = *(const float4*)&a_src[f];
    float4 d4 = *(const float4*)&a_dst[f];
    float ps = hv.x * s4.x + hv.y * s4.y + hv.z * s4.z + hv.w * s4.w;
    float pd = hv.x * d4.x + hv.y * d4.y + hv.z * d4.z + hv.w * d4.w;
    #pragma unroll
    for (int off = 8; off; off >>= 1) {
        ps += __shfl_down_sync(0xffffffffu, ps, off, 16);
        pd += __shfl_down_sync(0xffffffffu, pd, off, 16);
    }
    if ((lane & 15) == 0) {
        int head = lane >> 4;
        g_as[w * 2 + head] = ps;
        g_ad[w * 2 + head] = pd;
    }
}

// ---------------- fused segment softmax + aggregation -----------------------
// one warp per destination node; self-loop handled analytically.
// Single online-softmax pass over edges for (max, expsum), then feature pass.
template <bool FINAL>
__global__ void agg_kernel(const float* __restrict__ bias,
                           const float* __restrict__ Wr,
                           const float* __restrict__ br_ptr,
                           float* __restrict__ out, int n) {
    int d = (blockIdx.x * blockDim.x + threadIdx.x) >> 5;
    int lane = threadIdx.x & 31;
    if (d >= n) return;

    int rs = g_rowptr[d], re = g_rowptr[d + 1];
    const float2* as2 = (const float2*)g_as;
    float2 add = *(const float2*)&g_ad[d * 2];
    float ad0 = add.x, ad1 = add.y;
    float2 asd = as2[d];
    float es0 = leaky(asd.x + ad0);
    float es1 = leaky(asd.y + ad1);

    // online softmax over edges (self-loop seeds lane 0). m init = self logit
    // (finite) on every lane so the merge never sees -inf - -inf.
    float m0 = es0, m1 = es1;
    float p0 = (lane == 0) ? 1.f : 0.f;
    float p1 = p0;
    for (int i = rs + lane; i < re; i += 32) {
        int s = g_csrc[i];
        float2 a = as2[s];
        float e0 = leaky(a.x + ad0);
        float e1 = leaky(a.y + ad1);
        float nm0 = fmaxf(m0, e0);
        float nm1 = fmaxf(m1, e1);
        p0 = p0 * __expf(m0 - nm0) + __expf(e0 - nm0);
        p1 = p1 * __expf(m1 - nm1) + __expf(e1 - nm1);
        m0 = nm0; m1 = nm1;
    }
    #pragma unroll
    for (int off = 16; off; off >>= 1) {
        float om0 = __shfl_xor_sync(0xffffffffu, m0, off);
        float op0 = __shfl_xor_sync(0xffffffffu, p0, off);
        float om1 = __shfl_xor_sync(0xffffffffu, m1, off);
        float op1 = __shfl_xor_sync(0xffffffffu, p1, off);
        float nm0 = fmaxf(m0, om0);
        float nm1 = fmaxf(m1, om1);
        p0 = p0 * __expf(m0 - nm0) + op0 * __expf(om0 - nm0);
        p1 = p1 * __expf(m1 - nm1) + op1 * __expf(om1 - nm1);
        m0 = nm0; m1 = nm1;
    }
    float r0 = __fdividef(1.f, p0);
    float r1 = __fdividef(1.f, p1);

    // feature pass: weighted accumulation (4 floats per lane)
    int f = lane * 4;
    int head = lane >> 4;
    float mh  = head ? m1 : m0;
    float rh  = head ? r1 : r0;
    float adh = head ? ad1 : ad0;
    float esh = head ? es1 : es0;

    float4 acc;
    {
        float a_self = __expf(esh - mh) * rh;
        float4 v = *(const float4*)&g_hlin[d * 128 + f];
        acc.x = a_self * v.x; acc.y = a_self * v.y;
        acc.z = a_self * v.z; acc.w = a_self * v.w;
    }
    // software-prefetched edge loop
    int i = rs;
    int sN = 0; float4 vN = make_float4(0, 0, 0, 0); float asN = 0.f;
    if (i < re) {
        sN = g_csrc[i];
        vN = *(const float4*)&g_hlin[sN * 128 + f];
        asN = g_as[sN * 2 + head];
    }
    while (i < re) {
        float4 v = vN; float a_s = asN;
        int in = i + 1;
        if (in < re) {
            sN = g_csrc[in];
            vN = *(const float4*)&g_hlin[sN * 128 + f];
            asN = g_as[sN * 2 + head];
        }
        float a = __expf(leaky(a_s + adh) - mh) * rh;
        acc.x += a * v.x; acc.y += a * v.y;
        acc.z += a * v.z; acc.w += a * v.w;
        i = in;
    }

    float4 bv = *(const float4*)&bias[f];
    float o0 = elu(acc.x + bv.x);
    float o1 = elu(acc.y + bv.y);
    float o2 = elu(acc.z + bv.z);
    float o3 = elu(acc.w + bv.w);

    if (!FINAL) {
        *(float4*)&g_hpost[d * 128 + f] = make_float4(o0, o1, o2, o3);
    } else {
        float4 wv = *(const float4*)&Wr[f];
        float p = o0 * wv.x + o1 * wv.y + o2 * wv.z + o3 * wv.w;
        #pragma unroll
        for (int off = 16; off; off >>= 1)
            p += __shfl_xor_sync(0xffffffffu, p, off);
        if (lane == 0) out[d] = p + br_ptr[0];
    }
}

// ---------------- launch ----------------------------------------------------
extern "C" void kernel_launch(void* const* d_in, const int* in_sizes, int n_in,
                              void* d_out, int out_size) {
    const float* x      = (const float*)d_in[0];
    const int*   eidx   = (const int*)  d_in[1];
    const float* W1     = (const float*)d_in[2];
    const float* a_src1 = (const float*)d_in[3];
    const float* a_dst1 = (const float*)d_in[4];
    const float* b1     = (const float*)d_in[5];
    const float* W2     = (const float*)d_in[6];
    const float* a_src2 = (const float*)d_in[7];
    const float* a_dst2 = (const float*)d_in[8];
    const float* b2     = (const float*)d_in[9];
    const float* Wr     = (const float*)d_in[10];
    const float* br     = (const float*)d_in[11];
    float* out = (float*)d_out;

    const int* src = eidx;          // edge_index[0]
    const int* dst = eidx + EE;     // edge_index[1]

    // --- build CSR over real edges (self-loops handled in aggregator) ---
    init_kernel<<<(NN + 255) / 256, 256>>>(NN);
    count_kernel<<<(EE + 255) / 256, 256>>>(dst, EE);
    scan_local_kernel<<<NB_SCAN, 1024>>>(NN);
    scan_bsums_kernel<<<1, 128>>>(NB_SCAN, NN);
    add_offsets_kernel<<<NB_SCAN, 1024>>>(NN);
    fill_kernel<<<(EE + 255) / 256, 256>>>(src, dst, EE);

    int gemm_blocks = (NN + 63) / 64;
    int warp_blocks = (NN + 7) / 8;     // 8 warps / 256-thread block

    // --- layer 1 ---
    gemm_kernel<true><<<gemm_blocks, 256>>>(x, W1, NN);
    alpha_kernel<<<warp_blocks, 256>>>(a_src1, a_dst1, NN);
    agg_kernel<false><<<warp_blocks, 256>>>(b1, nullptr, nullptr, nullptr, NN);

    // --- layer 2 (+ fused final linear) ---
    gemm_kernel<false><<<gemm_blocks, 256>>>(nullptr, W2, NN);
    alpha_kernel<<<warp_blocks, 256>>>(a_src2, a_dst2, NN);
    agg_kernel<true><<<warp_blocks, 256>>>(b2, Wr, br, out, NN);
}

// round 3
// speedup vs baseline: 1.1118x; 1.1118x over previous
#include <cuda_runtime.h>
#include <cuda_bf16.h>

// Problem constants (fixed by the dataset)
#define NN      100000
#define FIN     128
#define HEADS   2
#define CDIM    64
#define FOUT    128          // HEADS*CDIM
#define EE      1600000
#define NEG_SLOPE 0.2f

#define NB_SCAN ((NN + 1023) / 1024)   // 98

// ---------------- scratch (static device globals; no allocation) ------------
__device__ float g_hlin[NN * FOUT];    // post-GEMM features (gather source)
__device__ float g_hpost[NN * FOUT];   // layer output after bias+ELU
__device__ float g_as[NN * HEADS];
__device__ float g_ad[NN * HEADS];
__device__ int   g_deg[NN];
__device__ int   g_cursor[NN];
__device__ int   g_rowptr[NN];
__device__ int   g_csrc[EE];
__device__ int   g_total;

__device__ __forceinline__ float leaky(float e) {
    return fmaxf(e, NEG_SLOPE * e);
}
__device__ __forceinline__ float elu(float x) {
    return x > 0.f ? x : (__expf(x) - 1.f);
}

// ---------------- CSR build (4 kernels) -------------------------------------
__global__ void init_kernel(int n) {
    int i = blockIdx.x * blockDim.x + threadIdx.x;
    if (i < n) g_deg[i] = 0;
    if (i == 0) g_total = 0;
}

__global__ void count_kernel(const int* __restrict__ dst, int e) {
    int i = blockIdx.x * blockDim.x + threadIdx.x;
    if (i < e) atomicAdd(&g_deg[dst[i]], 1);
}

// Block-local inclusive scan; block base assigned via one atomic. Segment
// bases are NOT ordered by node id — re comes from rs + deg[d].
__global__ void scan_assign_kernel(int n) {
    __shared__ int sm[1024];
    __shared__ int sbase;
    int i = blockIdx.x * 1024 + threadIdx.x;
    int v = (i < n) ? g_deg[i] : 0;
    sm[threadIdx.x] = v;
    __syncthreads();
    #pragma unroll
    for (int off = 1; off < 1024; off <<= 1) {
        int t = (threadIdx.x >= off) ? sm[threadIdx.x - off] : 0;
        __syncthreads();
        sm[threadIdx.x] += t;
        __syncthreads();
    }
    if (threadIdx.x == 1023) sbase = atomicAdd(&g_total, sm[1023]);
    __syncthreads();
    if (i < n) {
        int rp = sbase + sm[threadIdx.x] - v;   // exclusive within block + base
        g_rowptr[i] = rp;
        g_cursor[i] = rp;
    }
}

__global__ void fill_kernel(const int* __restrict__ src, const int* __restrict__ dst, int e) {
    int i = blockIdx.x * blockDim.x + threadIdx.x;
    if (i < e) {
        int pos = atomicAdd(&g_cursor[dst[i]], 1);
        g_csrc[pos] = src[i];
    }
}

// ---------------- GEMM + fused alpha: [n,128] @ [128,128] -> g_hlin, g_as/ad -
// BM=128, BN=128, BK=16, 256 threads, 8x8 microtile.
// Thread (tx,ty): rows row0+ty*8+i, cols tx*4+jj (head0) and 64+tx*4+jj (head1).
template <bool FIRST>
__global__ void gemm_alpha_kernel(const float* __restrict__ xext,
                                  const float* __restrict__ W,
                                  const float* __restrict__ a_src,
                                  const float* __restrict__ a_dst, int n) {
    __shared__ float As[16][129];   // [k][row], pad kills 4-way store conflict
    __shared__ float Bs[16][128];   // [k][col]
    const float* A = FIRST ? xext : g_hpost;
    int tid = threadIdx.x;
    int tx = tid & 15, ty = tid >> 4;
    int row0 = blockIdx.x * 128;

    float acc[8][8];
    #pragma unroll
    for (int i = 0; i < 8; i++)
        #pragma unroll
        for (int j = 0; j < 8; j++) acc[i][j] = 0.f;

    for (int k0 = 0; k0 < 128; k0 += 16) {
        #pragma unroll
        for (int l = 0; l < 2; l++) {
            int e  = tid + l * 256;
            int r  = e >> 2;            // 0..127
            int kc = (e & 3) << 2;      // 0,4,8,12
            int gr = row0 + r;
            float4 v = make_float4(0.f, 0.f, 0.f, 0.f);
            if (gr < n) v = *(const float4*)&A[gr * 128 + k0 + kc];
            As[kc + 0][r] = v.x; As[kc + 1][r] = v.y;
            As[kc + 2][r] = v.z; As[kc + 3][r] = v.w;
        }
        #pragma unroll
        for (int l = 0; l < 2; l++) {
            int e  = tid + l * 256;
            int kr = e >> 5;            // 0..15
            int c  = (e & 31) << 2;     // 0..124
            *(float4*)&Bs[kr][c] = *(const float4*)&W[(k0 + kr) * 128 + c];
        }
        __syncthreads();
        #pragma unroll
        for (int kk = 0; kk < 16; kk++) {
            float a[8], b[8];
            #pragma unroll
            for (int i = 0; i < 8; i++) a[i] = As[kk][ty * 8 + i];
            float4 b0 = *(const float4*)&Bs[kk][tx * 4];
            float4 b1 = *(const float4*)&Bs[kk][64 + tx * 4];
            b[0] = b0.x; b[1] = b0.y; b[2] = b0.z; b[3] = b0.w;
            b[4] = b1.x; b[5] = b1.y; b[6] = b1.z; b[7] = b1.w;
            #pragma unroll
            for (int i = 0; i < 8; i++)
                #pragma unroll
                for (int j = 0; j < 8; j++) acc[i][j] += a[i] * b[j];
        }
        __syncthreads();
    }

    // epilogue: store h, and compute alpha_s / alpha_d via cross-tx reduction
    float4 s0 = *(const float4*)&a_src[tx * 4];
    float4 s1 = *(const float4*)&a_src[64 + tx * 4];
    float4 dd0 = *(const float4*)&a_dst[tx * 4];
    float4 dd1 = *(const float4*)&a_dst[64 + tx * 4];

    #pragma unroll
    for (int i = 0; i < 8; i++) {
        int gr = row0 + ty * 8 + i;
        bool ok = gr < n;
        if (ok) {
            *(float4*)&g_hlin[gr * 128 + tx * 4] =
                make_float4(acc[i][0], acc[i][1], acc[i][2], acc[i][3]);
            *(float4*)&g_hlin[gr * 128 + 64 + tx * 4] =
                make_float4(acc[i][4], acc[i][5], acc[i][6], acc[i][7]);
        }
        float ps0 = acc[i][0]*s0.x + acc[i][1]*s0.y + acc[i][2]*s0.z + acc[i][3]*s0.w;
        float ps1 = acc[i][4]*s1.x + acc[i][5]*s1.y + acc[i][6]*s1.z + acc[i][7]*s1.w;
        float pd0 = acc[i][0]*dd0.x + acc[i][1]*dd0.y + acc[i][2]*dd0.z + acc[i][3]*dd0.w;
        float pd1 = acc[i][4]*dd1.x + acc[i][5]*dd1.y + acc[i][6]*dd1.z + acc[i][7]*dd1.w;
        #pragma unroll
        for (int off = 8; off; off >>= 1) {
            ps0 += __shfl_down_sync(0xffffffffu, ps0, off, 16);
            ps1 += __shfl_down_sync(0xffffffffu, ps1, off, 16);
            pd0 += __shfl_down_sync(0xffffffffu, pd0, off, 16);
            pd1 += __shfl_down_sync(0xffffffffu, pd1, off, 16);
        }
        if (tx == 0 && ok) {
            g_as[gr * 2 + 0] = ps0; g_as[gr * 2 + 1] = ps1;
            g_ad[gr * 2 + 0] = pd0; g_ad[gr * 2 + 1] = pd1;
        }
    }
}

// ---------------- fused segment softmax + aggregation -----------------------
// one warp per destination node; self-loop handled analytically.
// Single online-softmax pass over edges for (max, expsum), then feature pass.
template <bool FINAL>
__global__ void agg_kernel(const float* __restrict__ bias,
                           const float* __restrict__ Wr,
                           const float* __restrict__ br_ptr,
                           float* __restrict__ out, int n) {
    int d = (blockIdx.x * blockDim.x + threadIdx.x) >> 5;
    int lane = threadIdx.x & 31;
    if (d >= n) return;

    int rs = g_rowptr[d];
    int re = rs + g_deg[d];
    const float2* as2 = (const float2*)g_as;
    float2 add = *(const float2*)&g_ad[d * 2];
    float ad0 = add.x, ad1 = add.y;
    float2 asd = as2[d];
    float es0 = leaky(asd.x + ad0);
    float es1 = leaky(asd.y + ad1);

    // online softmax over edges (self-loop seeds lane 0). m init = self logit
    // (finite) on every lane so the merge never sees -inf - -inf.
    float m0 = es0, m1 = es1;
    float p0 = (lane == 0) ? 1.f : 0.f;
    float p1 = p0;
    for (int i = rs + lane; i < re; i += 32) {
        int s = g_csrc[i];
        float2 a = as2[s];
        float e0 = leaky(a.x + ad0);
        float e1 = leaky(a.y + ad1);
        float nm0 = fmaxf(m0, e0);
        float nm1 = fmaxf(m1, e1);
        p0 = p0 * __expf(m0 - nm0) + __expf(e0 - nm0);
        p1 = p1 * __expf(m1 - nm1) + __expf(e1 - nm1);
        m0 = nm0; m1 = nm1;
    }
    #pragma unroll
    for (int off = 16; off; off >>= 1) {
        float om0 = __shfl_xor_sync(0xffffffffu, m0, off);
        float op0 = __shfl_xor_sync(0xffffffffu, p0, off);
        float om1 = __shfl_xor_sync(0xffffffffu, m1, off);
        float op1 = __shfl_xor_sync(0xffffffffu, p1, off);
        float nm0 = fmaxf(m0, om0);
        float nm1 = fmaxf(m1, om1);
        p0 = p0 * __expf(m0 - nm0) + op0 * __expf(om0 - nm0);
        p1 = p1 * __expf(m1 - nm1) + op1 * __expf(om1 - nm1);
        m0 = nm0; m1 = nm1;
    }
    float r0 = __fdividef(1.f, p0);
    float r1 = __fdividef(1.f, p1);

    // feature pass: weighted accumulation (4 floats per lane)
    int f = lane * 4;
    int head = lane >> 4;
    float mh  = head ? m1 : m0;
    float rh  = head ? r1 : r0;
    float adh = head ? ad1 : ad0;
    float esh = head ? es1 : es0;

    float4 acc;
    {
        float a_self = __expf(esh - mh) * rh;
        float4 v = *(const float4*)&g_hlin[d * 128 + f];
        acc.x = a_self * v.x; acc.y = a_self * v.y;
        acc.z = a_self * v.z; acc.w = a_self * v.w;
    }
    // software-prefetched edge loop
    int i = rs;
    int sN = 0; float4 vN = make_float4(0, 0, 0, 0); float asN = 0.f;
    if (i < re) {
        sN = g_csrc[i];
        vN = *(const float4*)&g_hlin[sN * 128 + f];
        asN = g_as[sN * 2 + head];
    }
    while (i < re) {
        float4 v = vN; float a_s = asN;
        int in = i + 1;
        if (in < re) {
            sN = g_csrc[in];
            vN = *(const float4*)&g_hlin[sN * 128 + f];
            asN = g_as[sN * 2 + head];
        }
        float a = __expf(leaky(a_s + adh) - mh) * rh;
        acc.x += a * v.x; acc.y += a * v.y;
        acc.z += a * v.z; acc.w += a * v.w;
        i = in;
    }

    float4 bv = *(const float4*)&bias[f];
    float o0 = elu(acc.x + bv.x);
    float o1 = elu(acc.y + bv.y);
    float o2 = elu(acc.z + bv.z);
    float o3 = elu(acc.w + bv.w);

    if (!FINAL) {
        *(float4*)&g_hpost[d * 128 + f] = make_float4(o0, o1, o2, o3);
    } else {
        float4 wv = *(const float4*)&Wr[f];
        float p = o0 * wv.x + o1 * wv.y + o2 * wv.z + o3 * wv.w;
        #pragma unroll
        for (int off = 16; off; off >>= 1)
            p += __shfl_xor_sync(0xffffffffu, p, off);
        if (lane == 0) out[d] = p + br_ptr[0];
    }
}

// ---------------- launch ----------------------------------------------------
extern "C" void kernel_launch(void* const* d_in, const int* in_sizes, int n_in,
                              void* d_out, int out_size) {
    const float* x      = (const float*)d_in[0];
    const int*   eidx   = (const int*)  d_in[1];
    const float* W1     = (const float*)d_in[2];
    const float* a_src1 = (const float*)d_in[3];
    const float* a_dst1 = (const float*)d_in[4];
    const float* b1     = (const float*)d_in[5];
    const float* W2     = (const float*)d_in[6];
    const float* a_src2 = (const float*)d_in[7];
    const float* a_dst2 = (const float*)d_in[8];
    const float* b2     = (const float*)d_in[9];
    const float* Wr     = (const float*)d_in[10];
    const float* br     = (const float*)d_in[11];
    float* out = (float*)d_out;

    const int* src = eidx;          // edge_index[0]
    const int* dst = eidx + EE;     // edge_index[1]

    int gemm_blocks = (NN + 127) / 128;
    int warp_blocks = (NN + 7) / 8;     // 8 warps / 256-thread block

    // --- build CSR over real edges (self-loops handled in aggregator) ---
    init_kernel<<<(NN + 255) / 256, 256>>>(NN);                 // launch 0
    count_kernel<<<(EE + 255) / 256, 256>>>(dst, EE);           // launch 1
    scan_assign_kernel<<<NB_SCAN, 1024>>>(NN);                  // launch 2
    fill_kernel<<<(EE + 255) / 256, 256>>>(src, dst, EE);       // launch 3

    // --- layer 1 ---
    gemm_alpha_kernel<true><<<gemm_blocks, 256>>>(x, W1, a_src1, a_dst1, NN);   // 4
    agg_kernel<false><<<warp_blocks, 256>>>(b1, nullptr, nullptr, nullptr, NN); // 5 (profiled)

    // --- layer 2 (+ fused final linear) ---
    gemm_alpha_kernel<false><<<gemm_blocks, 256>>>(nullptr, W2, a_src2, a_dst2, NN); // 6
    agg_kernel<true><<<warp_blocks, 256>>>(b2, Wr, br, out, NN);                     // 7
}

// round 4
// speedup vs baseline: 1.1699x; 1.0523x over previous
#include <cuda_runtime.h>
#include <cuda_fp16.h>
#include <cuda_bf16.h>

// Problem constants (fixed by the dataset)
#define NN      100000
#define FIN     128
#define HEADS   2
#define CDIM    64
#define FOUT    128          // HEADS*CDIM
#define EE      1600000
#define NEG_SLOPE 0.2f

#define NB_SCAN ((NN + 1023) / 1024)   // 98

// ---------------- scratch (static device globals; no allocation) ------------
__device__ __half g_hh[NN * FOUT];     // fp16 gather table (post-GEMM features)
__device__ float  g_hpost[NN * FOUT];  // layer-1 output after bias+ELU (GEMM2 in)
__device__ float  g_as[NN * HEADS];
__device__ float  g_ad[NN * HEADS];
__device__ int    g_deg[NN];
__device__ int    g_cursor[NN];
__device__ int    g_rowptr[NN];
__device__ int    g_csrc[EE];
__device__ int    g_total;

__device__ __forceinline__ float leaky(float e) {
    return fmaxf(e, NEG_SLOPE * e);
}
__device__ __forceinline__ float elu(float x) {
    return x > 0.f ? x : (__expf(x) - 1.f);
}

// ---------------- CSR build -------------------------------------------------
__global__ void init_kernel(int n) {
    int i = blockIdx.x * blockDim.x + threadIdx.x;
    if (i < n) g_deg[i] = 0;
    if (i == 0) g_total = 0;
}

// 4 edges per thread, int4 loads, 4 independent atomics (MLP=4)
__global__ void count_kernel(const int* __restrict__ dst, int e4) {
    int i = blockIdx.x * blockDim.x + threadIdx.x;
    if (i < e4) {
        int4 d = ((const int4*)dst)[i];
        atomicAdd(&g_deg[d.x], 1);
        atomicAdd(&g_deg[d.y], 1);
        atomicAdd(&g_deg[d.z], 1);
        atomicAdd(&g_deg[d.w], 1);
    }
}

// Block-local inclusive scan; block base assigned via one atomic. Segment
// bases are NOT ordered by node id — re comes from rs + deg[d].
__global__ void scan_assign_kernel(int n) {
    __shared__ int sm[1024];
    __shared__ int sbase;
    int i = blockIdx.x * 1024 + threadIdx.x;
    int v = (i < n) ? g_deg[i] : 0;
    sm[threadIdx.x] = v;
    __syncthreads();
    #pragma unroll
    for (int off = 1; off < 1024; off <<= 1) {
        int t = (threadIdx.x >= off) ? sm[threadIdx.x - off] : 0;
        __syncthreads();
        sm[threadIdx.x] += t;
        __syncthreads();
    }
    if (threadIdx.x == 1023) sbase = atomicAdd(&g_total, sm[1023]);
    __syncthreads();
    if (i < n) {
        int rp = sbase + sm[threadIdx.x] - v;   // exclusive within block + base
        g_rowptr[i] = rp;
        g_cursor[i] = rp;
    }
}

// 4 edges per thread, int4 loads
__global__ void fill_kernel(const int* __restrict__ src, const int* __restrict__ dst, int e4) {
    int i = blockIdx.x * blockDim.x + threadIdx.x;
    if (i < e4) {
        int4 d = ((const int4*)dst)[i];
        int4 s = ((const int4*)src)[i];
        int p0 = atomicAdd(&g_cursor[d.x], 1);
        int p1 = atomicAdd(&g_cursor[d.y], 1);
        int p2 = atomicAdd(&g_cursor[d.z], 1);
        int p3 = atomicAdd(&g_cursor[d.w], 1);
        g_csrc[p0] = s.x;
        g_csrc[p1] = s.y;
        g_csrc[p2] = s.z;
        g_csrc[p3] = s.w;
    }
}

// ---------------- GEMM + fused alpha: [n,128] @ [128,128] -> g_hh, g_as/ad --
// BM=128, BN=128, BK=16, 256 threads, 8x8 microtile.
template <bool FIRST>
__global__ void gemm_alpha_kernel(const float* __restrict__ xext,
                                  const float* __restrict__ W,
                                  const float* __restrict__ a_src,
                                  const float* __restrict__ a_dst, int n) {
    __shared__ float As[16][129];   // [k][row]
    __shared__ float Bs[16][128];   // [k][col]
    const float* A = FIRST ? xext : g_hpost;
    int tid = threadIdx.x;
    int tx = tid & 15, ty = tid >> 4;
    int row0 = blockIdx.x * 128;

    float acc[8][8];
    #pragma unroll
    for (int i = 0; i < 8; i++)
        #pragma unroll
        for (int j = 0; j < 8; j++) acc[i][j] = 0.f;

    for (int k0 = 0; k0 < 128; k0 += 16) {
        #pragma unroll
        for (int l = 0; l < 2; l++) {
            int e  = tid + l * 256;
            int r  = e >> 2;
            int kc = (e & 3) << 2;
            int gr = row0 + r;
            float4 v = make_float4(0.f, 0.f, 0.f, 0.f);
            if (gr < n) v = *(const float4*)&A[gr * 128 + k0 + kc];
            As[kc + 0][r] = v.x; As[kc + 1][r] = v.y;
            As[kc + 2][r] = v.z; As[kc + 3][r] = v.w;
        }
        #pragma unroll
        for (int l = 0; l < 2; l++) {
            int e  = tid + l * 256;
            int kr = e >> 5;
            int c  = (e & 31) << 2;
            *(float4*)&Bs[kr][c] = *(const float4*)&W[(k0 + kr) * 128 + c];
        }
        __syncthreads();
        #pragma unroll
        for (int kk = 0; kk < 16; kk++) {
            float a[8], b[8];
            #pragma unroll
            for (int i = 0; i < 8; i++) a[i] = As[kk][ty * 8 + i];
            float4 b0 = *(const float4*)&Bs[kk][tx * 4];
            float4 b1 = *(const float4*)&Bs[kk][64 + tx * 4];
            b[0] = b0.x; b[1] = b0.y; b[2] = b0.z; b[3] = b0.w;
            b[4] = b1.x; b[5] = b1.y; b[6] = b1.z; b[7] = b1.w;
            #pragma unroll
            for (int i = 0; i < 8; i++)
                #pragma unroll
                for (int j = 0; j < 8; j++) acc[i][j] += a[i] * b[j];
        }
        __syncthreads();
    }

    // epilogue: store fp16 h and compute alpha_s / alpha_d via cross-tx reduce
    float4 s0 = *(const float4*)&a_src[tx * 4];
    float4 s1 = *(const float4*)&a_src[64 + tx * 4];
    float4 dd0 = *(const float4*)&a_dst[tx * 4];
    float4 dd1 = *(const float4*)&a_dst[64 + tx * 4];

    #pragma unroll
    for (int i = 0; i < 8; i++) {
        int gr = row0 + ty * 8 + i;
        bool ok = gr < n;
        if (ok) {
            __half2 h01 = __floats2half2_rn(acc[i][0], acc[i][1]);
            __half2 h23 = __floats2half2_rn(acc[i][2], acc[i][3]);
            __half2 h45 = __floats2half2_rn(acc[i][4], acc[i][5]);
            __half2 h67 = __floats2half2_rn(acc[i][6], acc[i][7]);
            uint2 u0, u1;
            u0.x = *(unsigned*)&h01; u0.y = *(unsigned*)&h23;
            u1.x = *(unsigned*)&h45; u1.y = *(unsigned*)&h67;
            *(uint2*)&g_hh[gr * 128 + tx * 4] = u0;
            *(uint2*)&g_hh[gr * 128 + 64 + tx * 4] = u1;
        }
        float ps0 = acc[i][0]*s0.x + acc[i][1]*s0.y + acc[i][2]*s0.z + acc[i][3]*s0.w;
        float ps1 = acc[i][4]*s1.x + acc[i][5]*s1.y + acc[i][6]*s1.z + acc[i][7]*s1.w;
        float pd0 = acc[i][0]*dd0.x + acc[i][1]*dd0.y + acc[i][2]*dd0.z + acc[i][3]*dd0.w;
        float pd1 = acc[i][4]*dd1.x + acc[i][5]*dd1.y + acc[i][6]*dd1.z + acc[i][7]*dd1.w;
        #pragma unroll
        for (int off = 8; off; off >>= 1) {
            ps0 += __shfl_down_sync(0xffffffffu, ps0, off, 16);
            ps1 += __shfl_down_sync(0xffffffffu, ps1, off, 16);
            pd0 += __shfl_down_sync(0xffffffffu, pd0, off, 16);
            pd1 += __shfl_down_sync(0xffffffffu, pd1, off, 16);
        }
        if (tx == 0 && ok) {
            g_as[gr * 2 + 0] = ps0; g_as[gr * 2 + 1] = ps1;
            g_ad[gr * 2 + 0] = pd0; g_ad[gr * 2 + 1] = pd1;
        }
    }
}

// ---------------- fused segment softmax + aggregation -----------------------
// one warp per destination node; self-loop handled analytically.
template <bool FINAL>
__global__ void agg_kernel(const float* __restrict__ bias,
                           const float* __restrict__ Wr,
                           const float* __restrict__ br_ptr,
                           float* __restrict__ out, int n) {
    int d = (blockIdx.x * blockDim.x + threadIdx.x) >> 5;
    int lane = threadIdx.x & 31;
    if (d >= n) return;

    int rs = g_rowptr[d];
    int re = rs + g_deg[d];
    const float2* as2 = (const float2*)g_as;
    float2 add = *(const float2*)&g_ad[d * 2];
    float ad0 = add.x, ad1 = add.y;
    float2 asd = as2[d];
    float es0 = leaky(asd.x + ad0);
    float es1 = leaky(asd.y + ad1);

    // online softmax over edges (self-loop seeds lane 0; m init = self logit,
    // finite on every lane so the merge never sees -inf - -inf)
    float m0 = es0, m1 = es1;
    float p0 = (lane == 0) ? 1.f : 0.f;
    float p1 = p0;
    for (int i = rs + lane; i < re; i += 32) {
        int s = g_csrc[i];
        float2 a = as2[s];
        float e0 = leaky(a.x + ad0);
        float e1 = leaky(a.y + ad1);
        float nm0 = fmaxf(m0, e0);
        float nm1 = fmaxf(m1, e1);
        p0 = p0 * __expf(m0 - nm0) + __expf(e0 - nm0);
        p1 = p1 * __expf(m1 - nm1) + __expf(e1 - nm1);
        m0 = nm0; m1 = nm1;
    }
    #pragma unroll
    for (int off = 16; off; off >>= 1) {
        float om0 = __shfl_xor_sync(0xffffffffu, m0, off);
        float op0 = __shfl_xor_sync(0xffffffffu, p0, off);
        float om1 = __shfl_xor_sync(0xffffffffu, m1, off);
        float op1 = __shfl_xor_sync(0xffffffffu, p1, off);
        float nm0 = fmaxf(m0, om0);
        float nm1 = fmaxf(m1, om1);
        p0 = p0 * __expf(m0 - nm0) + op0 * __expf(om0 - nm0);
        p1 = p1 * __expf(m1 - nm1) + op1 * __expf(om1 - nm1);
        m0 = nm0; m1 = nm1;
    }
    float r0 = __fdividef(1.f, p0);
    float r1 = __fdividef(1.f, p1);

    // feature pass: weighted accumulation (4 fp16 features per lane)
    int f = lane * 4;
    int head = lane >> 4;
    float mh  = head ? m1 : m0;
    float rh  = head ? r1 : r0;
    float adh = head ? ad1 : ad0;
    float esh = head ? es1 : es0;

    float4 acc;
    {
        float a_self = __expf(esh - mh) * rh;
        uint2 u = *(const uint2*)&g_hh[d * 128 + f];
        float2 lo = __half22float2(*(__half2*)&u.x);
        float2 hi = __half22float2(*(__half2*)&u.y);
        acc.x = a_self * lo.x; acc.y = a_self * lo.y;
        acc.z = a_self * hi.x; acc.w = a_self * hi.y;
    }
    // software-prefetched edge loop
    int i = rs;
    uint2 uN = make_uint2(0, 0); float asN = 0.f;
    if (i < re) {
        int sN = g_csrc[i];
        uN = *(const uint2*)&g_hh[sN * 128 + f];
        asN = g_as[sN * 2 + head];
    }
    while (i < re) {
        uint2 u = uN; float a_s = asN;
        int in = i + 1;
        if (in < re) {
            int sN = g_csrc[in];
            uN = *(const uint2*)&g_hh[sN * 128 + f];
            asN = g_as[sN * 2 + head];
        }
        float a = __expf(leaky(a_s + adh) - mh) * rh;
        float2 lo = __half22float2(*(__half2*)&u.x);
        float2 hi = __half22float2(*(__half2*)&u.y);
        acc.x += a * lo.x; acc.y += a * lo.y;
        acc.z += a * hi.x; acc.w += a * hi.y;
        i = in;
    }

    float4 bv = *(const float4*)&bias[f];
    float o0 = elu(acc.x + bv.x);
    float o1 = elu(acc.y + bv.y);
    float o2 = elu(acc.z + bv.z);
    float o3 = elu(acc.w + bv.w);

    if (!FINAL) {
        *(float4*)&g_hpost[d * 128 + f] = make_float4(o0, o1, o2, o3);
    } else {
        float4 wv = *(const float4*)&Wr[f];
        float p = o0 * wv.x + o1 * wv.y + o2 * wv.z + o3 * wv.w;
        #pragma unroll
        for (int off = 16; off; off >>= 1)
            p += __shfl_xor_sync(0xffffffffu, p, off);
        if (lane == 0) out[d] = p + br_ptr[0];
    }
}

// ---------------- launch ----------------------------------------------------
extern "C" void kernel_launch(void* const* d_in, const int* in_sizes, int n_in,
                              void* d_out, int out_size) {
    const float* x      = (const float*)d_in[0];
    const int*   eidx   = (const int*)  d_in[1];
    const float* W1     = (const float*)d_in[2];
    const float* a_src1 = (const float*)d_in[3];
    const float* a_dst1 = (const float*)d_in[4];
    const float* b1     = (const float*)d_in[5];
    const float* W2     = (const float*)d_in[6];
    const float* a_src2 = (const float*)d_in[7];
    const float* a_dst2 = (const float*)d_in[8];
    const float* b2     = (const float*)d_in[9];
    const float* Wr     = (const float*)d_in[10];
    const float* br     = (const float*)d_in[11];
    float* out = (float*)d_out;

    const int* src = eidx;          // edge_index[0]
    const int* dst = eidx + EE;     // edge_index[1]

    int gemm_blocks = (NN + 127) / 128;
    int warp_blocks = (NN + 7) / 8;     // 8 warps / 256-thread block
    int e4 = EE / 4;                    // EE divisible by 4

    init_kernel<<<(NN + 255) / 256, 256>>>(NN);                 // 0
    count_kernel<<<(e4 + 255) / 256, 256>>>(dst, e4);           // 1
    scan_assign_kernel<<<NB_SCAN, 1024>>>(NN);                  // 2
    gemm_alpha_kernel<true><<<gemm_blocks, 256>>>(x, W1, a_src1, a_dst1, NN); // 3 (profiled)
    fill_kernel<<<(e4 + 255) / 256, 256>>>(src, dst, e4);       // 4

    agg_kernel<false><<<warp_blocks, 256>>>(b1, nullptr, nullptr, nullptr, NN); // 5

    gemm_alpha_kernel<false><<<gemm_blocks, 256>>>(nullptr, W2, a_src2, a_dst2, NN); // 6
    agg_kernel<true><<<warp_blocks, 256>>>(b2, Wr, br, out, NN);                     // 7
}

// round 5
// speedup vs baseline: 1.4397x; 1.2307x over previous
#include <cuda_runtime.h>
#include <cuda_fp16.h>
#include <cuda_bf16.h>

// Problem constants (fixed by the dataset)
#define NN      100000
#define FIN     128
#define HEADS   2
#define CDIM    64
#define FOUT    128          // HEADS*CDIM
#define EE      1600000
#define NEG_SLOPE 0.2f

#define NB_SCAN ((NN + 1023) / 1024)   // 98

// ---------------- scratch (static device globals; no allocation) ------------
__device__ __half g_hh[NN * FOUT];     // fp16 gather table (post-GEMM features)
__device__ float  g_hpost[NN * FOUT];  // layer-1 output after bias+ELU (GEMM2 in)
__device__ float  g_as[NN * HEADS];
__device__ float  g_ad[NN * HEADS];
__device__ int    g_deg[NN];
__device__ int    g_cursor[NN];
__device__ int    g_rowptr[NN];
__device__ int    g_csrc[EE];
__device__ int    g_total;

__device__ __forceinline__ float leaky(float e) {
    return fmaxf(e, NEG_SLOPE * e);
}
__device__ __forceinline__ float elu(float x) {
    return x > 0.f ? x : (__expf(x) - 1.f);
}

// ---------------- CSR build -------------------------------------------------
__global__ void init_kernel(int n) {
    int i = blockIdx.x * blockDim.x + threadIdx.x;
    if (i < n) g_deg[i] = 0;
    if (i == 0) g_total = 0;
}

__global__ void count_kernel(const int* __restrict__ dst, int e4) {
    int i = blockIdx.x * blockDim.x + threadIdx.x;
    if (i < e4) {
        int4 d = ((const int4*)dst)[i];
        atomicAdd(&g_deg[d.x], 1);
        atomicAdd(&g_deg[d.y], 1);
        atomicAdd(&g_deg[d.z], 1);
        atomicAdd(&g_deg[d.w], 1);
    }
}

__global__ void scan_assign_kernel(int n) {
    __shared__ int sm[1024];
    __shared__ int sbase;
    int i = blockIdx.x * 1024 + threadIdx.x;
    int v = (i < n) ? g_deg[i] : 0;
    sm[threadIdx.x] = v;
    __syncthreads();
    #pragma unroll
    for (int off = 1; off < 1024; off <<= 1) {
        int t = (threadIdx.x >= off) ? sm[threadIdx.x - off] : 0;
        __syncthreads();
        sm[threadIdx.x] += t;
        __syncthreads();
    }
    if (threadIdx.x == 1023) sbase = atomicAdd(&g_total, sm[1023]);
    __syncthreads();
    if (i < n) {
        int rp = sbase + sm[threadIdx.x] - v;
        g_rowptr[i] = rp;
        g_cursor[i] = rp;
    }
}

__global__ void fill_kernel(const int* __restrict__ src, const int* __restrict__ dst, int e4) {
    int i = blockIdx.x * blockDim.x + threadIdx.x;
    if (i < e4) {
        int4 d = ((const int4*)dst)[i];
        int4 s = ((const int4*)src)[i];
        int p0 = atomicAdd(&g_cursor[d.x], 1);
        int p1 = atomicAdd(&g_cursor[d.y], 1);
        int p2 = atomicAdd(&g_cursor[d.z], 1);
        int p3 = atomicAdd(&g_cursor[d.w], 1);
        g_csrc[p0] = s.x;
        g_csrc[p1] = s.y;
        g_csrc[p2] = s.z;
        g_csrc[p3] = s.w;
    }
}

// ---------------- tensor-core helpers ---------------------------------------
__device__ __forceinline__ void ldsm_x4(unsigned& r0, unsigned& r1, unsigned& r2, unsigned& r3,
                                        unsigned addr) {
    asm volatile("ldmatrix.sync.aligned.m8n8.x4.shared.b16 {%0,%1,%2,%3},[%4];\n"
                 : "=r"(r0), "=r"(r1), "=r"(r2), "=r"(r3) : "r"(addr));
}
__device__ __forceinline__ void ldsm_x2t(unsigned& r0, unsigned& r1, unsigned addr) {
    asm volatile("ldmatrix.sync.aligned.m8n8.x2.trans.shared.b16 {%0,%1},[%2];\n"
                 : "=r"(r0), "=r"(r1) : "r"(addr));
}
__device__ __forceinline__ void mma_bf16(float* d, const unsigned* a, unsigned b0, unsigned b1) {
    asm volatile("mma.sync.aligned.m16n8k16.row.col.f32.bf16.bf16.f32 "
                 "{%0,%1,%2,%3},{%4,%5,%6,%7},{%8,%9},{%0,%1,%2,%3};\n"
                 : "+f"(d[0]), "+f"(d[1]), "+f"(d[2]), "+f"(d[3])
                 : "r"(a[0]), "r"(a[1]), "r"(a[2]), "r"(a[3]), "r"(b0), "r"(b1));
}
__device__ __forceinline__ void split_bf16(float v, __nv_bfloat16& hi, __nv_bfloat16& lo) {
    hi = __float2bfloat16_rn(v);
    lo = __float2bfloat16_rn(v - __bfloat162float(hi));
}

// ---------------- GEMM (3xBF16 split) + fused alpha -------------------------
// C[n,128] = A[n,128] @ W[128,128]; BM=128, BN=128(full), BK=32 chunks.
// 8 warps: wm in 0..3 (32 rows), wn in 0..1 (64 cols = one head).
#define A_STRIDE 40    // 32 + 8 pad (bf16 elems)
#define B_STRIDE 136   // 128 + 8 pad
template <bool FIRST>
__global__ void __launch_bounds__(256, 2)
gemm_alpha_kernel(const float* __restrict__ xext,
                  const float* __restrict__ W,
                  const float* __restrict__ a_src,
                  const float* __restrict__ a_dst, int n) {
    __shared__ __nv_bfloat16 sAh[128][A_STRIDE];
    __shared__ __nv_bfloat16 sAl[128][A_STRIDE];
    __shared__ __nv_bfloat16 sBh[32][B_STRIDE];
    __shared__ __nv_bfloat16 sBl[32][B_STRIDE];

    const float* A = FIRST ? xext : g_hpost;
    int tid = threadIdx.x;
    int wid = tid >> 5, lane = tid & 31;
    int wm = wid >> 1, wn = wid & 1;
    int row0 = blockIdx.x * 128;
    int mrow = wm * 32;
    int ncol = wn * 64;

    unsigned ah_base = (unsigned)__cvta_generic_to_shared(&sAh[0][0]);
    unsigned al_base = (unsigned)__cvta_generic_to_shared(&sAl[0][0]);
    unsigned bh_base = (unsigned)__cvta_generic_to_shared(&sBh[0][0]);
    unsigned bl_base = (unsigned)__cvta_generic_to_shared(&sBl[0][0]);

    float acc[2][8][4];
    #pragma unroll
    for (int mi = 0; mi < 2; mi++)
        #pragma unroll
        for (int nt = 0; nt < 8; nt++)
            #pragma unroll
            for (int q = 0; q < 4; q++) acc[mi][nt][q] = 0.f;

    for (int kc = 0; kc < 4; kc++) {
        // load+convert A chunk: 128 rows x 32 cols
        #pragma unroll
        for (int p = 0; p < 4; p++) {
            int idx = p * 256 + tid;
            int r = idx >> 3;
            int c4 = (idx & 7) << 2;
            int gr = row0 + r;
            float4 v = (gr < n) ? *(const float4*)&A[gr * 128 + kc * 32 + c4]
                                : make_float4(0.f, 0.f, 0.f, 0.f);
            __nv_bfloat16 h0, l0, h1, l1, h2, l2, h3, l3;
            split_bf16(v.x, h0, l0); split_bf16(v.y, h1, l1);
            split_bf16(v.z, h2, l2); split_bf16(v.w, h3, l3);
            *(__nv_bfloat162*)&sAh[r][c4]     = __nv_bfloat162(h0, h1);
            *(__nv_bfloat162*)&sAh[r][c4 + 2] = __nv_bfloat162(h2, h3);
            *(__nv_bfloat162*)&sAl[r][c4]     = __nv_bfloat162(l0, l1);
            *(__nv_bfloat162*)&sAl[r][c4 + 2] = __nv_bfloat162(l2, l3);
        }
        // load+convert B chunk: 32 k-rows x 128 cols
        #pragma unroll
        for (int p = 0; p < 4; p++) {
            int idx = p * 256 + tid;
            int k = idx >> 5;
            int n4 = (idx & 31) << 2;
            float4 v = *(const float4*)&W[(kc * 32 + k) * 128 + n4];
            __nv_bfloat16 h0, l0, h1, l1, h2, l2, h3, l3;
            split_bf16(v.x, h0, l0); split_bf16(v.y, h1, l1);
            split_bf16(v.z, h2, l2); split_bf16(v.w, h3, l3);
            *(__nv_bfloat162*)&sBh[k][n4]     = __nv_bfloat162(h0, h1);
            *(__nv_bfloat162*)&sBh[k][n4 + 2] = __nv_bfloat162(h2, h3);
            *(__nv_bfloat162*)&sBl[k][n4]     = __nv_bfloat162(l0, l1);
            *(__nv_bfloat162*)&sBl[k][n4 + 2] = __nv_bfloat162(l2, l3);
        }
        __syncthreads();

        #pragma unroll
        for (int ks = 0; ks < 2; ks++) {
            unsigned ah[2][4], al[2][4];
            #pragma unroll
            for (int mi = 0; mi < 2; mi++) {
                int r = mrow + mi * 16 + (lane & 15);
                int c = ks * 16 + ((lane >> 4) << 3);
                unsigned off = (unsigned)(r * A_STRIDE + c) * 2u;
                ldsm_x4(ah[mi][0], ah[mi][1], ah[mi][2], ah[mi][3], ah_base + off);
                ldsm_x4(al[mi][0], al[mi][1], al[mi][2], al[mi][3], al_base + off);
            }
            #pragma unroll
            for (int nt = 0; nt < 8; nt++) {
                int krow = ks * 16 + (lane & 15);
                int bcol = ncol + nt * 8;
                unsigned off = (unsigned)(krow * B_STRIDE + bcol) * 2u;
                unsigned bh0, bh1, bl0, bl1;
                ldsm_x2t(bh0, bh1, bh_base + off);
                ldsm_x2t(bl0, bl1, bl_base + off);
                #pragma unroll
                for (int mi = 0; mi < 2; mi++) {
                    mma_bf16(acc[mi][nt], ah[mi], bh0, bh1);   // hi*hi
                    mma_bf16(acc[mi][nt], ah[mi], bl0, bl1);   // hi*lo
                    mma_bf16(acc[mi][nt], al[mi], bh0, bh1);   // lo*hi
                }
            }
        }
        __syncthreads();
    }

    // ---------------- epilogue: fp16 table store + alpha logits -------------
    int g   = lane >> 2;   // row-in-8
    int tig = lane & 3;    // col-pair id

    float asv[16], adv[16];
    #pragma unroll
    for (int nt = 0; nt < 8; nt++) {
        int c = ncol + nt * 8 + tig * 2;
        asv[nt * 2]     = a_src[c];
        asv[nt * 2 + 1] = a_src[c + 1];
        adv[nt * 2]     = a_dst[c];
        adv[nt * 2 + 1] = a_dst[c + 1];
    }

    #pragma unroll
    for (int mi = 0; mi < 2; mi++) {
        int r_lo = row0 + mrow + mi * 16 + g;
        int r_hi = r_lo + 8;
        bool ok_lo = r_lo < n, ok_hi = r_hi < n;
        float ps_lo = 0.f, pd_lo = 0.f, ps_hi = 0.f, pd_hi = 0.f;
        #pragma unroll
        for (int nt = 0; nt < 8; nt++) {
            float c0 = acc[mi][nt][0], c1 = acc[mi][nt][1];
            float c2 = acc[mi][nt][2], c3 = acc[mi][nt][3];
            ps_lo += c0 * asv[nt * 2] + c1 * asv[nt * 2 + 1];
            pd_lo += c0 * adv[nt * 2] + c1 * adv[nt * 2 + 1];
            ps_hi += c2 * asv[nt * 2] + c3 * asv[nt * 2 + 1];
            pd_hi += c2 * adv[nt * 2] + c3 * adv[nt * 2 + 1];
            int col = ncol + nt * 8 + tig * 2;
            if (ok_lo) *(__half2*)&g_hh[r_lo * 128 + col] = __floats2half2_rn(c0, c1);
            if (ok_hi) *(__half2*)&g_hh[r_hi * 128 + col] = __floats2half2_rn(c2, c3);
        }
        #pragma unroll
        for (int off = 1; off < 4; off <<= 1) {
            ps_lo += __shfl_xor_sync(0xffffffffu, ps_lo, off);
            pd_lo += __shfl_xor_sync(0xffffffffu, pd_lo, off);
            ps_hi += __shfl_xor_sync(0xffffffffu, ps_hi, off);
            pd_hi += __shfl_xor_sync(0xffffffffu, pd_hi, off);
        }
        if (tig == 0) {
            if (ok_lo) { g_as[r_lo * 2 + wn] = ps_lo; g_ad[r_lo * 2 + wn] = pd_lo; }
            if (ok_hi) { g_as[r_hi * 2 + wn] = ps_hi; g_ad[r_hi * 2 + wn] = pd_hi; }
        }
    }
}

// ---------------- fused segment softmax + aggregation -----------------------
template <bool FINAL>
__global__ void agg_kernel(const float* __restrict__ bias,
                           const float* __restrict__ Wr,
                           const float* __restrict__ br_ptr,
                           float* __restrict__ out, int n) {
    int d = (blockIdx.x * blockDim.x + threadIdx.x) >> 5;
    int lane = threadIdx.x & 31;
    if (d >= n) return;

    int rs = g_rowptr[d];
    int re = rs + g_deg[d];
    const float2* as2 = (const float2*)g_as;
    float2 add = *(const float2*)&g_ad[d * 2];
    float ad0 = add.x, ad1 = add.y;
    float2 asd = as2[d];
    float es0 = leaky(asd.x + ad0);
    float es1 = leaky(asd.y + ad1);

    float m0 = es0, m1 = es1;
    float p0 = (lane == 0) ? 1.f : 0.f;
    float p1 = p0;
    for (int i = rs + lane; i < re; i += 32) {
        int s = g_csrc[i];
        float2 a = as2[s];
        float e0 = leaky(a.x + ad0);
        float e1 = leaky(a.y + ad1);
        float nm0 = fmaxf(m0, e0);
        float nm1 = fmaxf(m1, e1);
        p0 = p0 * __expf(m0 - nm0) + __expf(e0 - nm0);
        p1 = p1 * __expf(m1 - nm1) + __expf(e1 - nm1);
        m0 = nm0; m1 = nm1;
    }
    #pragma unroll
    for (int off = 16; off; off >>= 1) {
        float om0 = __shfl_xor_sync(0xffffffffu, m0, off);
        float op0 = __shfl_xor_sync(0xffffffffu, p0, off);
        float om1 = __shfl_xor_sync(0xffffffffu, m1, off);
        float op1 = __shfl_xor_sync(0xffffffffu, p1, off);
        float nm0 = fmaxf(m0, om0);
        float nm1 = fmaxf(m1, om1);
        p0 = p0 * __expf(m0 - nm0) + op0 * __expf(om0 - nm0);
        p1 = p1 * __expf(m1 - nm1) + op1 * __expf(om1 - nm1);
        m0 = nm0; m1 = nm1;
    }
    float r0 = __fdividef(1.f, p0);
    float r1 = __fdividef(1.f, p1);

    int f = lane * 4;
    int head = lane >> 4;
    float mh  = head ? m1 : m0;
    float rh  = head ? r1 : r0;
    float adh = head ? ad1 : ad0;
    float esh = head ? es1 : es0;

    float4 acc;
    {
        float a_self = __expf(esh - mh) * rh;
        uint2 u = *(const uint2*)&g_hh[d * 128 + f];
        float2 lo = __half22float2(*(__half2*)&u.x);
        float2 hi = __half22float2(*(__half2*)&u.y);
        acc.x = a_self * lo.x; acc.y = a_self * lo.y;
        acc.z = a_self * hi.x; acc.w = a_self * hi.y;
    }
    int i = rs;
    uint2 uN = make_uint2(0, 0); float asN = 0.f;
    if (i < re) {
        int sN = g_csrc[i];
        uN = *(const uint2*)&g_hh[sN * 128 + f];
        asN = g_as[sN * 2 + head];
    }
    while (i < re) {
        uint2 u = uN; float a_s = asN;
        int in = i + 1;
        if (in < re) {
            int sN = g_csrc[in];
            uN = *(const uint2*)&g_hh[sN * 128 + f];
            asN = g_as[sN * 2 + head];
        }
        float a = __expf(leaky(a_s + adh) - mh) * rh;
        float2 lo = __half22float2(*(__half2*)&u.x);
        float2 hi = __half22float2(*(__half2*)&u.y);
        acc.x += a * lo.x; acc.y += a * lo.y;
        acc.z += a * hi.x; acc.w += a * hi.y;
        i = in;
    }

    float4 bv = *(const float4*)&bias[f];
    float o0 = elu(acc.x + bv.x);
    float o1 = elu(acc.y + bv.y);
    float o2 = elu(acc.z + bv.z);
    float o3 = elu(acc.w + bv.w);

    if (!FINAL) {
        *(float4*)&g_hpost[d * 128 + f] = make_float4(o0, o1, o2, o3);
    } else {
        float4 wv = *(const float4*)&Wr[f];
        float p = o0 * wv.x + o1 * wv.y + o2 * wv.z + o3 * wv.w;
        #pragma unroll
        for (int off = 16; off; off >>= 1)
            p += __shfl_xor_sync(0xffffffffu, p, off);
        if (lane == 0) out[d] = p + br_ptr[0];
    }
}

// ---------------- launch ----------------------------------------------------
extern "C" void kernel_launch(void* const* d_in, const int* in_sizes, int n_in,
                              void* d_out, int out_size) {
    const float* x      = (const float*)d_in[0];
    const int*   eidx   = (const int*)  d_in[1];
    const float* W1     = (const float*)d_in[2];
    const float* a_src1 = (const float*)d_in[3];
    const float* a_dst1 = (const float*)d_in[4];
    const float* b1     = (const float*)d_in[5];
    const float* W2     = (const float*)d_in[6];
    const float* a_src2 = (const float*)d_in[7];
    const float* a_dst2 = (const float*)d_in[8];
    const float* b2     = (const float*)d_in[9];
    const float* Wr     = (const float*)d_in[10];
    const float* br     = (const float*)d_in[11];
    float* out = (float*)d_out;

    const int* src = eidx;          // edge_index[0]
    const int* dst = eidx + EE;     // edge_index[1]

    int gemm_blocks = (NN + 127) / 128;
    int warp_blocks = (NN + 7) / 8;
    int e4 = EE / 4;

    init_kernel<<<(NN + 255) / 256, 256>>>(NN);                 // 0
    count_kernel<<<(e4 + 255) / 256, 256>>>(dst, e4);           // 1
    scan_assign_kernel<<<NB_SCAN, 1024>>>(NN);                  // 2
    gemm_alpha_kernel<true><<<gemm_blocks, 256>>>(x, W1, a_src1, a_dst1, NN); // 3 (profiled)
    fill_kernel<<<(e4 + 255) / 256, 256>>>(src, dst, e4);       // 4

    agg_kernel<false><<<warp_blocks, 256>>>(b1, nullptr, nullptr, nullptr, NN); // 5

    gemm_alpha_kernel<false><<<gemm_blocks, 256>>>(nullptr, W2, a_src2, a_dst2, NN); // 6
    agg_kernel<true><<<warp_blocks, 256>>>(b2, Wr, br, out, NN);                     // 7
}

// round 7
// speedup vs baseline: 1.7143x; 1.1907x over previous
#include <cuda_runtime.h>
#include <cuda_fp16.h>
#include <cuda_bf16.h>

// Problem constants (fixed by the dataset)
#define NN      100000
#define FIN     128
#define HEADS   2
#define CDIM    64
#define FOUT    128          // HEADS*CDIM
#define EE      1600000
#define NEG_SLOPE 0.2f

#define NB_SCAN ((NN + 1023) / 1024)   // 98

// ---------------- scratch (static device globals; no allocation) ------------
__device__ __half g_hh[NN * FOUT];     // fp16 gather table (post-GEMM features)
__device__ float  g_hpost[NN * FOUT];  // layer-1 output after bias+ELU (GEMM2 in)
__device__ float  g_as[NN * HEADS];
__device__ float  g_ad[NN * HEADS];
__device__ int    g_deg[NN];
__device__ int    g_cursor[NN];
__device__ int    g_rowptr[NN];
__device__ int    g_csrc[EE];
__device__ int    g_total;

__device__ __forceinline__ float leaky(float e) {
    return fmaxf(e, NEG_SLOPE * e);
}
__device__ __forceinline__ float elu(float x) {
    return x > 0.f ? x : (__expf(x) - 1.f);
}

// ---------------- CSR build -------------------------------------------------
__global__ void init_kernel(int n4) {
    int i = blockIdx.x * blockDim.x + threadIdx.x;
    if (i < n4) ((int4*)g_deg)[i] = make_int4(0, 0, 0, 0);
    if (i == 0) g_total = 0;
}

__global__ void count_kernel(const int* __restrict__ dst, int e4) {
    int i = blockIdx.x * blockDim.x + threadIdx.x;
    if (i < e4) {
        int4 d = ((const int4*)dst)[i];
        atomicAdd(&g_deg[d.x], 1);
        atomicAdd(&g_deg[d.y], 1);
        atomicAdd(&g_deg[d.z], 1);
        atomicAdd(&g_deg[d.w], 1);
    }
}

__global__ void scan_assign_kernel(int n) {
    __shared__ int sm[1024];
    __shared__ int sbase;
    int i = blockIdx.x * 1024 + threadIdx.x;
    int v = (i < n) ? g_deg[i] : 0;
    sm[threadIdx.x] = v;
    __syncthreads();
    #pragma unroll
    for (int off = 1; off < 1024; off <<= 1) {
        int t = (threadIdx.x >= off) ? sm[threadIdx.x - off] : 0;
        __syncthreads();
        sm[threadIdx.x] += t;
        __syncthreads();
    }
    if (threadIdx.x == 1023) sbase = atomicAdd(&g_total, sm[1023]);
    __syncthreads();
    if (i < n) {
        int rp = sbase + sm[threadIdx.x] - v;
        g_rowptr[i] = rp;
        g_cursor[i] = rp;
    }
}

__global__ void fill_kernel(const int* __restrict__ src, const int* __restrict__ dst, int e4) {
    int i = blockIdx.x * blockDim.x + threadIdx.x;
    if (i < e4) {
        int4 d = ((const int4*)dst)[i];
        int4 s = ((const int4*)src)[i];
        int p0 = atomicAdd(&g_cursor[d.x], 1);
        int p1 = atomicAdd(&g_cursor[d.y], 1);
        int p2 = atomicAdd(&g_cursor[d.z], 1);
        int p3 = atomicAdd(&g_cursor[d.w], 1);
        g_csrc[p0] = s.x;
        g_csrc[p1] = s.y;
        g_csrc[p2] = s.z;
        g_csrc[p3] = s.w;
    }
}

// ---------------- tensor-core helpers ---------------------------------------
__device__ __forceinline__ void ldsm_x4(unsigned& r0, unsigned& r1, unsigned& r2, unsigned& r3,
                                        unsigned addr) {
    asm volatile("ldmatrix.sync.aligned.m8n8.x4.shared.b16 {%0,%1,%2,%3},[%4];\n"
                 : "=r"(r0), "=r"(r1), "=r"(r2), "=r"(r3) : "r"(addr));
}
__device__ __forceinline__ void ldsm_x2t(unsigned& r0, unsigned& r1, unsigned addr) {
    asm volatile("ldmatrix.sync.aligned.m8n8.x2.trans.shared.b16 {%0,%1},[%2];\n"
                 : "=r"(r0), "=r"(r1) : "r"(addr));
}
__device__ __forceinline__ void mma_bf16(float* d, const unsigned* a, unsigned b0, unsigned b1) {
    asm volatile("mma.sync.aligned.m16n8k16.row.col.f32.bf16.bf16.f32 "
                 "{%0,%1,%2,%3},{%4,%5,%6,%7},{%8,%9},{%0,%1,%2,%3};\n"
                 : "+f"(d[0]), "+f"(d[1]), "+f"(d[2]), "+f"(d[3])
                 : "r"(a[0]), "r"(a[1]), "r"(a[2]), "r"(a[3]), "r"(b0), "r"(b1));
}
__device__ __forceinline__ void split_bf16(float v, __nv_bfloat16& hi, __nv_bfloat16& lo) {
    hi = __float2bfloat16_rn(v);
    lo = __float2bfloat16_rn(v - __bfloat162float(hi));
}

// ---------------- GEMM (3xBF16 split) + fused alpha -------------------------
#define A_STRIDE 40
#define B_STRIDE 136
template <bool FIRST>
__global__ void __launch_bounds__(256, 2)
gemm_alpha_kernel(const float* __restrict__ xext,
                  const float* __restrict__ W,
                  const float* __restrict__ a_src,
                  const float* __restrict__ a_dst, int n) {
    __shared__ __nv_bfloat16 sAh[128][A_STRIDE];
    __shared__ __nv_bfloat16 sAl[128][A_STRIDE];
    __shared__ __nv_bfloat16 sBh[32][B_STRIDE];
    __shared__ __nv_bfloat16 sBl[32][B_STRIDE];

    const float* A = FIRST ? xext : g_hpost;
    int tid = threadIdx.x;
    int wid = tid >> 5, lane = tid & 31;
    int wm = wid >> 1, wn = wid & 1;
    int row0 = blockIdx.x * 128;
    int mrow = wm * 32;
    int ncol = wn * 64;

    unsigned ah_base = (unsigned)__cvta_generic_to_shared(&sAh[0][0]);
    unsigned al_base = (unsigned)__cvta_generic_to_shared(&sAl[0][0]);
    unsigned bh_base = (unsigned)__cvta_generic_to_shared(&sBh[0][0]);
    unsigned bl_base = (unsigned)__cvta_generic_to_shared(&sBl[0][0]);

    float acc[2][8][4];
    #pragma unroll
    for (int mi = 0; mi < 2; mi++)
        #pragma unroll
        for (int nt = 0; nt < 8; nt++)
            #pragma unroll
            for (int q = 0; q < 4; q++) acc[mi][nt][q] = 0.f;

    for (int kc = 0; kc < 4; kc++) {
        #pragma unroll
        for (int p = 0; p < 4; p++) {
            int idx = p * 256 + tid;
            int r = idx >> 3;
            int c4 = (idx & 7) << 2;
            int gr = row0 + r;
            float4 v = (gr < n) ? *(const float4*)&A[gr * 128 + kc * 32 + c4]
                                : make_float4(0.f, 0.f, 0.f, 0.f);
            __nv_bfloat16 h0, l0, h1, l1, h2, l2, h3, l3;
            split_bf16(v.x, h0, l0); split_bf16(v.y, h1, l1);
            split_bf16(v.z, h2, l2); split_bf16(v.w, h3, l3);
            *(__nv_bfloat162*)&sAh[r][c4]     = __nv_bfloat162(h0, h1);
            *(__nv_bfloat162*)&sAh[r][c4 + 2] = __nv_bfloat162(h2, h3);
            *(__nv_bfloat162*)&sAl[r][c4]     = __nv_bfloat162(l0, l1);
            *(__nv_bfloat162*)&sAl[r][c4 + 2] = __nv_bfloat162(l2, l3);
        }
        #pragma unroll
        for (int p = 0; p < 4; p++) {
            int idx = p * 256 + tid;
            int k = idx >> 5;
            int n4 = (idx & 31) << 2;
            float4 v = *(const float4*)&W[(kc * 32 + k) * 128 + n4];
            __nv_bfloat16 h0, l0, h1, l1, h2, l2, h3, l3;
            split_bf16(v.x, h0, l0); split_bf16(v.y, h1, l1);
            split_bf16(v.z, h2, l2); split_bf16(v.w, h3, l3);
            *(__nv_bfloat162*)&sBh[k][n4]     = __nv_bfloat162(h0, h1);
            *(__nv_bfloat162*)&sBh[k][n4 + 2] = __nv_bfloat162(h2, h3);
            *(__nv_bfloat162*)&sBl[k][n4]     = __nv_bfloat162(l0, l1);
            *(__nv_bfloat162*)&sBl[k][n4 + 2] = __nv_bfloat162(l2, l3);
        }
        __syncthreads();

        #pragma unroll
        for (int ks = 0; ks < 2; ks++) {
            unsigned ah[2][4], al[2][4];
            #pragma unroll
            for (int mi = 0; mi < 2; mi++) {
                int r = mrow + mi * 16 + (lane & 15);
                int c = ks * 16 + ((lane >> 4) << 3);
                unsigned off = (unsigned)(r * A_STRIDE + c) * 2u;
                ldsm_x4(ah[mi][0], ah[mi][1], ah[mi][2], ah[mi][3], ah_base + off);
                ldsm_x4(al[mi][0], al[mi][1], al[mi][2], al[mi][3], al_base + off);
            }
            #pragma unroll
            for (int nt = 0; nt < 8; nt++) {
                int krow = ks * 16 + (lane & 15);
                int bcol = ncol + nt * 8;
                unsigned off = (unsigned)(krow * B_STRIDE + bcol) * 2u;
                unsigned bh0, bh1, bl0, bl1;
                ldsm_x2t(bh0, bh1, bh_base + off);
                ldsm_x2t(bl0, bl1, bl_base + off);
                #pragma unroll
                for (int mi = 0; mi < 2; mi++) {
                    mma_bf16(acc[mi][nt], ah[mi], bh0, bh1);
                    mma_bf16(acc[mi][nt], ah[mi], bl0, bl1);
                    mma_bf16(acc[mi][nt], al[mi], bh0, bh1);
                }
            }
        }
        __syncthreads();
    }

    // epilogue: fp16 table store + alpha logits
    int g   = lane >> 2;
    int tig = lane & 3;

    float asv[16], adv[16];
    #pragma unroll
    for (int nt = 0; nt < 8; nt++) {
        int c = ncol + nt * 8 + tig * 2;
        asv[nt * 2]     = a_src[c];
        asv[nt * 2 + 1] = a_src[c + 1];
        adv[nt * 2]     = a_dst[c];
        adv[nt * 2 + 1] = a_dst[c + 1];
    }

    #pragma unroll
    for (int mi = 0; mi < 2; mi++) {
        int r_lo = row0 + mrow + mi * 16 + g;
        int r_hi = r_lo + 8;
        bool ok_lo = r_lo < n, ok_hi = r_hi < n;
        float ps_lo = 0.f, pd_lo = 0.f, ps_hi = 0.f, pd_hi = 0.f;
        #pragma unroll
        for (int nt = 0; nt < 8; nt++) {
            float c0 = acc[mi][nt][0], c1 = acc[mi][nt][1];
            float c2 = acc[mi][nt][2], c3 = acc[mi][nt][3];
            ps_lo += c0 * asv[nt * 2] + c1 * asv[nt * 2 + 1];
            pd_lo += c0 * adv[nt * 2] + c1 * adv[nt * 2 + 1];
            ps_hi += c2 * asv[nt * 2] + c3 * asv[nt * 2 + 1];
            pd_hi += c2 * adv[nt * 2] + c3 * adv[nt * 2 + 1];
            int col = ncol + nt * 8 + tig * 2;
            if (ok_lo) *(__half2*)&g_hh[r_lo * 128 + col] = __floats2half2_rn(c0, c1);
            if (ok_hi) *(__half2*)&g_hh[r_hi * 128 + col] = __floats2half2_rn(c2, c3);
        }
        #pragma unroll
        for (int off = 1; off < 4; off <<= 1) {
            ps_lo += __shfl_xor_sync(0xffffffffu, ps_lo, off);
            pd_lo += __shfl_xor_sync(0xffffffffu, pd_lo, off);
            ps_hi += __shfl_xor_sync(0xffffffffu, ps_hi, off);
            pd_hi += __shfl_xor_sync(0xffffffffu, pd_hi, off);
        }
        if (tig == 0) {
            if (ok_lo) { g_as[r_lo * 2 + wn] = ps_lo; g_ad[r_lo * 2 + wn] = pd_lo; }
            if (ok_hi) { g_as[r_hi * 2 + wn] = ps_hi; g_ad[r_hi * 2 + wn] = pd_hi; }
        }
    }
}

// ---------------- one-pass softmax aggregation ------------------------------
// w = exp(leaky(logit)) accumulated un-normalized; logits are bounded (|e|<~25)
// so no max subtraction is needed in fp32. Unroll-4 for MLP.
template <bool FINAL>
__global__ void agg_kernel(const float* __restrict__ bias,
                           const float* __restrict__ Wr,
                           const float* __restrict__ br_ptr,
                           float* __restrict__ out, int n) {
    int d = (blockIdx.x * blockDim.x + threadIdx.x) >> 5;
    int lane = threadIdx.x & 31;
    if (d >= n) return;

    int rs = g_rowptr[d];
    int re = rs + g_deg[d];
    int head = lane >> 4;
    int f = lane * 4;

    float adh = g_ad[d * 2 + head];
    float w_self = __expf(leaky(g_as[d * 2 + head] + adh));

    float p = w_self;
    float4 acc;
    {
        uint2 u = *(const uint2*)&g_hh[d * 128 + f];
        float2 lo = __half22float2(*(__half2*)&u.x);
        float2 hi = __half22float2(*(__half2*)&u.y);
        acc.x = w_self * lo.x; acc.y = w_self * lo.y;
        acc.z = w_self * hi.x; acc.w = w_self * hi.y;
    }

    int i = rs;
    for (; i + 4 <= re; i += 4) {
        int s0 = g_csrc[i], s1 = g_csrc[i + 1], s2 = g_csrc[i + 2], s3 = g_csrc[i + 3];
        float a0 = g_as[s0 * 2 + head];
        float a1 = g_as[s1 * 2 + head];
        float a2 = g_as[s2 * 2 + head];
        float a3 = g_as[s3 * 2 + head];
        uint2 u0 = *(const uint2*)&g_hh[s0 * 128 + f];
        uint2 u1 = *(const uint2*)&g_hh[s1 * 128 + f];
        uint2 u2 = *(const uint2*)&g_hh[s2 * 128 + f];
        uint2 u3 = *(const uint2*)&g_hh[s3 * 128 + f];
        float w0 = __expf(leaky(a0 + adh));
        float w1 = __expf(leaky(a1 + adh));
        float w2 = __expf(leaky(a2 + adh));
        float w3 = __expf(leaky(a3 + adh));
        p += (w0 + w1) + (w2 + w3);
        float2 l0 = __half22float2(*(__half2*)&u0.x), h0 = __half22float2(*(__half2*)&u0.y);
        float2 l1 = __half22float2(*(__half2*)&u1.x), h1 = __half22float2(*(__half2*)&u1.y);
        float2 l2 = __half22float2(*(__half2*)&u2.x), h2 = __half22float2(*(__half2*)&u2.y);
        float2 l3 = __half22float2(*(__half2*)&u3.x), h3 = __half22float2(*(__half2*)&u3.y);
        acc.x += w0 * l0.x + w1 * l1.x + w2 * l2.x + w3 * l3.x;
        acc.y += w0 * l0.y + w1 * l1.y + w2 * l2.y + w3 * l3.y;
        acc.z += w0 * h0.x + w1 * h1.x + w2 * h2.x + w3 * h3.x;
        acc.w += w0 * h0.y + w1 * h1.y + w2 * h2.y + w3 * h3.y;
    }
    for (; i < re; i++) {
        int s = g_csrc[i];
        float a_s = g_as[s * 2 + head];
        uint2 u = *(const uint2*)&g_hh[s * 128 + f];
        float w = __expf(leaky(a_s + adh));
        p += w;
        float2 lo = __half22float2(*(__half2*)&u.x);
        float2 hi = __half22float2(*(__half2*)&u.y);
        acc.x += w * lo.x; acc.y += w * lo.y;
        acc.z += w * hi.x; acc.w += w * hi.y;
    }

    float rh = __fdividef(1.f, p);
    float4 bv = *(const float4*)&bias[f];
    float o0 = elu(acc.x * rh + bv.x);
    float o1 = elu(acc.y * rh + bv.y);
    float o2 = elu(acc.z * rh + bv.z);
    float o3 = elu(acc.w * rh + bv.w);

    if (!FINAL) {
        *(float4*)&g_hpost[d * 128 + f] = make_float4(o0, o1, o2, o3);
    } else {
        float4 wv = *(const float4*)&Wr[f];
        float pr = o0 * wv.x + o1 * wv.y + o2 * wv.z + o3 * wv.w;
        #pragma unroll
        for (int off = 16; off; off >>= 1)
            pr += __shfl_xor_sync(0xffffffffu, pr, off);
        if (lane == 0) out[d] = pr + br_ptr[0];
    }
}

// ---------------- launch (single stream; graph-capture safe) ----------------
extern "C" void kernel_launch(void* const* d_in, const int* in_sizes, int n_in,
                              void* d_out, int out_size) {
    const float* x      = (const float*)d_in[0];
    const int*   eidx   = (const int*)  d_in[1];
    const float* W1     = (const float*)d_in[2];
    const float* a_src1 = (const float*)d_in[3];
    const float* a_dst1 = (const float*)d_in[4];
    const float* b1     = (const float*)d_in[5];
    const float* W2     = (const float*)d_in[6];
    const float* a_src2 = (const float*)d_in[7];
    const float* a_dst2 = (const float*)d_in[8];
    const float* b2     = (const float*)d_in[9];
    const float* Wr     = (const float*)d_in[10];
    const float* br     = (const float*)d_in[11];
    float* out = (float*)d_out;

    const int* src = eidx;
    const int* dst = eidx + EE;

    int gemm_blocks = (NN + 127) / 128;
    int warp_blocks = (NN + 7) / 8;
    int e4 = EE / 4;
    int n4 = NN / 4;

    init_kernel<<<(n4 + 255) / 256, 256>>>(n4);                  // 0
    count_kernel<<<(e4 + 255) / 256, 256>>>(dst, e4);            // 1
    scan_assign_kernel<<<NB_SCAN, 1024>>>(NN);                   // 2
    gemm_alpha_kernel<true><<<gemm_blocks, 256>>>(x, W1, a_src1, a_dst1, NN); // 3 (profiled)
    fill_kernel<<<(e4 + 255) / 256, 256>>>(src, dst, e4);        // 4

    agg_kernel<false><<<warp_blocks, 256>>>(b1, nullptr, nullptr, nullptr, NN); // 5
    gemm_alpha_kernel<false><<<gemm_blocks, 256>>>(nullptr, W2, a_src2, a_dst2, NN); // 6
    agg_kernel<true><<<warp_blocks, 256>>>(b2, Wr, br, out, NN);                     // 7
}

// round 10
// speedup vs baseline: 1.7464x; 1.0187x over previous
#include <cuda_runtime.h>
#include <cuda_fp16.h>
#include <cuda_bf16.h>

// Problem constants (fixed by the dataset)
#define NN      100000
#define FIN     128
#define HEADS   2
#define CDIM    64
#define FOUT    128          // HEADS*CDIM
#define EE      1600000
#define NEG_SLOPE 0.2f

#define NB_SCAN ((NN + 1023) / 1024)   // 98

// ---------------- scratch (static device globals; no allocation) ------------
__device__ __half         g_hh[NN * FOUT];    // fp16 gather table
__device__ __nv_bfloat16  g_hph[NN * FOUT];   // layer-1 output, bf16 hi part
__device__ __nv_bfloat16  g_hpl[NN * FOUT];   // layer-1 output, bf16 lo part
__device__ __nv_bfloat16  g_w1h[FIN * FOUT], g_w1l[FIN * FOUT];
__device__ __nv_bfloat16  g_w2h[FOUT * FOUT], g_w2l[FOUT * FOUT];
__device__ float  g_as[NN * HEADS];
__device__ float  g_ad[NN * HEADS];
__device__ int    g_deg[NN];
__device__ int    g_cursor[NN];
__device__ int    g_rowptr[NN];
__device__ int    g_csrc[EE];
__device__ int    g_total;

__device__ __forceinline__ float leaky(float e) {
    return fmaxf(e, NEG_SLOPE * e);
}
__device__ __forceinline__ float elu(float x) {
    return x > 0.f ? x : (__expf(x) - 1.f);
}
__device__ __forceinline__ void split_bf16(float v, __nv_bfloat16& hi, __nv_bfloat16& lo) {
    hi = __float2bfloat16_rn(v);
    lo = __float2bfloat16_rn(v - __bfloat162float(hi));
}

// ---------------- W pre-split ------------------------------------------------
__global__ void wsplit_kernel(const float* __restrict__ W1, const float* __restrict__ W2) {
    int i = blockIdx.x * blockDim.x + threadIdx.x;
    if (i < FIN * FOUT) {
        __nv_bfloat16 h, l;
        split_bf16(W1[i], h, l);
        g_w1h[i] = h; g_w1l[i] = l;
    } else if (i < FIN * FOUT + FOUT * FOUT) {
        int j = i - FIN * FOUT;
        __nv_bfloat16 h, l;
        split_bf16(W2[j], h, l);
        g_w2h[j] = h; g_w2l[j] = l;
    }
}

// ---------------- CSR build -------------------------------------------------
__global__ void init_kernel(int n4) {
    int i = blockIdx.x * blockDim.x + threadIdx.x;
    if (i < n4) ((int4*)g_deg)[i] = make_int4(0, 0, 0, 0);
    if (i == 0) g_total = 0;
}

__global__ void count_kernel(const int* __restrict__ dst, int e4) {
    int i = blockIdx.x * blockDim.x + threadIdx.x;
    if (i < e4) {
        int4 d = ((const int4*)dst)[i];
        atomicAdd(&g_deg[d.x], 1);
        atomicAdd(&g_deg[d.y], 1);
        atomicAdd(&g_deg[d.z], 1);
        atomicAdd(&g_deg[d.w], 1);
    }
}

__global__ void scan_assign_kernel(int n) {
    __shared__ int sm[1024];
    __shared__ int sbase;
    int i = blockIdx.x * 1024 + threadIdx.x;
    int v = (i < n) ? g_deg[i] : 0;
    sm[threadIdx.x] = v;
    __syncthreads();
    #pragma unroll
    for (int off = 1; off < 1024; off <<= 1) {
        int t = (threadIdx.x >= off) ? sm[threadIdx.x - off] : 0;
        __syncthreads();
        sm[threadIdx.x] += t;
        __syncthreads();
    }
    if (threadIdx.x == 1023) sbase = atomicAdd(&g_total, sm[1023]);
    __syncthreads();
    if (i < n) {
        int rp = sbase + sm[threadIdx.x] - v;
        g_rowptr[i] = rp;
        g_cursor[i] = rp;
    }
}

__global__ void fill_kernel(const int* __restrict__ src, const int* __restrict__ dst, int e4) {
    int i = blockIdx.x * blockDim.x + threadIdx.x;
    if (i < e4) {
        int4 d = ((const int4*)dst)[i];
        int4 s = ((const int4*)src)[i];
        int p0 = atomicAdd(&g_cursor[d.x], 1);
        int p1 = atomicAdd(&g_cursor[d.y], 1);
        int p2 = atomicAdd(&g_cursor[d.z], 1);
        int p3 = atomicAdd(&g_cursor[d.w], 1);
        g_csrc[p0] = s.x;
        g_csrc[p1] = s.y;
        g_csrc[p2] = s.z;
        g_csrc[p3] = s.w;
    }
}

// ---------------- tensor-core helpers ---------------------------------------
__device__ __forceinline__ void ldsm_x4(unsigned& r0, unsigned& r1, unsigned& r2, unsigned& r3,
                                        unsigned addr) {
    asm volatile("ldmatrix.sync.aligned.m8n8.x4.shared.b16 {%0,%1,%2,%3},[%4];\n"
                 : "=r"(r0), "=r"(r1), "=r"(r2), "=r"(r3) : "r"(addr));
}
__device__ __forceinline__ void ldsm_x4t(unsigned& r0, unsigned& r1, unsigned& r2, unsigned& r3,
                                         unsigned addr) {
    asm volatile("ldmatrix.sync.aligned.m8n8.x4.trans.shared.b16 {%0,%1,%2,%3},[%4];\n"
                 : "=r"(r0), "=r"(r1), "=r"(r2), "=r"(r3) : "r"(addr));
}
__device__ __forceinline__ void mma_bf16(float* d, const unsigned* a, unsigned b0, unsigned b1) {
    asm volatile("mma.sync.aligned.m16n8k16.row.col.f32.bf16.bf16.f32 "
                 "{%0,%1,%2,%3},{%4,%5,%6,%7},{%8,%9},{%0,%1,%2,%3};\n"
                 : "+f"(d[0]), "+f"(d[1]), "+f"(d[2]), "+f"(d[3])
                 : "r"(a[0]), "r"(a[1]), "r"(a[2]), "r"(a[3]), "r"(b0), "r"(b1));
}

// ---------------- GEMM (3xBF16 split) + fused alpha -------------------------
// FIRST: A = x (f32, split on the fly). !FIRST: A = pre-split g_hph/g_hpl.
// B (W) always pre-split in global bf16.
#define A_STRIDE 40
#define B_STRIDE 136
template <bool FIRST>
__global__ void __launch_bounds__(256, 2)
gemm_alpha_kernel(const float* __restrict__ xext,
                  const float* __restrict__ a_src,
                  const float* __restrict__ a_dst, int n) {
    __shared__ __nv_bfloat16 sAh[128][A_STRIDE];
    __shared__ __nv_bfloat16 sAl[128][A_STRIDE];
    __shared__ __nv_bfloat16 sBh[32][B_STRIDE];
    __shared__ __nv_bfloat16 sBl[32][B_STRIDE];

    const __nv_bfloat16* Wh = FIRST ? g_w1h : g_w2h;
    const __nv_bfloat16* Wl = FIRST ? g_w1l : g_w2l;

    int tid = threadIdx.x;
    int wid = tid >> 5, lane = tid & 31;
    int wm = wid >> 1, wn = wid & 1;
    int row0 = blockIdx.x * 128;
    int mrow = wm * 32;
    int ncol = wn * 64;

    unsigned ah_base = (unsigned)__cvta_generic_to_shared(&sAh[0][0]);
    unsigned al_base = (unsigned)__cvta_generic_to_shared(&sAl[0][0]);
    unsigned bh_base = (unsigned)__cvta_generic_to_shared(&sBh[0][0]);
    unsigned bl_base = (unsigned)__cvta_generic_to_shared(&sBl[0][0]);

    float acc[2][8][4];
    #pragma unroll
    for (int mi = 0; mi < 2; mi++)
        #pragma unroll
        for (int nt = 0; nt < 8; nt++)
            #pragma unroll
            for (int q = 0; q < 4; q++) acc[mi][nt][q] = 0.f;

    for (int kc = 0; kc < 4; kc++) {
        // ---- A chunk: 128 rows x 32 cols ----
        if (FIRST) {
            #pragma unroll
            for (int p = 0; p < 4; p++) {
                int idx = p * 256 + tid;
                int r = idx >> 3;
                int c4 = (idx & 7) << 2;
                int gr = row0 + r;
                float4 v = (gr < n) ? *(const float4*)&xext[gr * 128 + kc * 32 + c4]
                                    : make_float4(0.f, 0.f, 0.f, 0.f);
                __nv_bfloat16 h0, l0, h1, l1, h2, l2, h3, l3;
                split_bf16(v.x, h0, l0); split_bf16(v.y, h1, l1);
                split_bf16(v.z, h2, l2); split_bf16(v.w, h3, l3);
                *(__nv_bfloat162*)&sAh[r][c4]     = __nv_bfloat162(h0, h1);
                *(__nv_bfloat162*)&sAh[r][c4 + 2] = __nv_bfloat162(h2, h3);
                *(__nv_bfloat162*)&sAl[r][c4]     = __nv_bfloat162(l0, l1);
                *(__nv_bfloat162*)&sAl[r][c4 + 2] = __nv_bfloat162(l2, l3);
            }
        } else {
            // pre-split bf16: 8 bf16 (16B) per chunk
            #pragma unroll
            for (int p = 0; p < 2; p++) {
                int idx = p * 256 + tid;
                int r = idx >> 2;
                int c = (idx & 3) << 3;
                int gr = row0 + r;
                uint4 vh = make_uint4(0, 0, 0, 0), vl = make_uint4(0, 0, 0, 0);
                if (gr < n) {
                    vh = *(const uint4*)&g_hph[gr * 128 + kc * 32 + c];
                    vl = *(const uint4*)&g_hpl[gr * 128 + kc * 32 + c];
                }
                *(uint4*)&sAh[r][c] = vh;
                *(uint4*)&sAl[r][c] = vl;
            }
        }
        // ---- B chunk: 32 k-rows x 128 cols, pre-split bf16 ----
        #pragma unroll
        for (int p = 0; p < 2; p++) {
            int idx = p * 256 + tid;
            int k = idx >> 4;
            int c = (idx & 15) << 3;
            *(uint4*)&sBh[k][c] = *(const uint4*)&Wh[(kc * 32 + k) * 128 + c];
            *(uint4*)&sBl[k][c] = *(const uint4*)&Wl[(kc * 32 + k) * 128 + c];
        }
        __syncthreads();

        #pragma unroll
        for (int ks = 0; ks < 2; ks++) {
            unsigned ah[2][4], al[2][4];
            #pragma unroll
            for (int mi = 0; mi < 2; mi++) {
                int r = mrow + mi * 16 + (lane & 15);
                int c = ks * 16 + ((lane >> 4) << 3);
                unsigned off = (unsigned)(r * A_STRIDE + c) * 2u;
                ldsm_x4(ah[mi][0], ah[mi][1], ah[mi][2], ah[mi][3], ah_base + off);
                ldsm_x4(al[mi][0], al[mi][1], al[mi][2], al[mi][3], al_base + off);
            }
            #pragma unroll
            for (int nt = 0; nt < 8; nt += 2) {
                int krow = ks * 16 + (lane & 15);
                int bcol = ncol + nt * 8 + ((lane >> 4) << 3);
                unsigned off = (unsigned)(krow * B_STRIDE + bcol) * 2u;
                unsigned bh0, bh1, bh2, bh3, bl0, bl1, bl2, bl3;
                ldsm_x4t(bh0, bh1, bh2, bh3, bh_base + off);
                ldsm_x4t(bl0, bl1, bl2, bl3, bl_base + off);
                #pragma unroll
                for (int mi = 0; mi < 2; mi++) {
                    mma_bf16(acc[mi][nt], ah[mi], bh0, bh1);
                    mma_bf16(acc[mi][nt], ah[mi], bl0, bl1);
                    mma_bf16(acc[mi][nt], al[mi], bh0, bh1);
                    mma_bf16(acc[mi][nt + 1], ah[mi], bh2, bh3);
                    mma_bf16(acc[mi][nt + 1], ah[mi], bl2, bl3);
                    mma_bf16(acc[mi][nt + 1], al[mi], bh2, bh3);
                }
            }
        }
        __syncthreads();
    }

    // epilogue: fp16 table store + alpha logits
    int g   = lane >> 2;
    int tig = lane & 3;

    float asv[16], adv[16];
    #pragma unroll
    for (int nt = 0; nt < 8; nt++) {
        int c = ncol + nt * 8 + tig * 2;
        asv[nt * 2]     = a_src[c];
        asv[nt * 2 + 1] = a_src[c + 1];
        adv[nt * 2]     = a_dst[c];
        adv[nt * 2 + 1] = a_dst[c + 1];
    }

    #pragma unroll
    for (int mi = 0; mi < 2; mi++) {
        int r_lo = row0 + mrow + mi * 16 + g;
        int r_hi = r_lo + 8;
        bool ok_lo = r_lo < n, ok_hi = r_hi < n;
        float ps_lo = 0.f, pd_lo = 0.f, ps_hi = 0.f, pd_hi = 0.f;
        #pragma unroll
        for (int nt = 0; nt < 8; nt++) {
            float c0 = acc[mi][nt][0], c1 = acc[mi][nt][1];
            float c2 = acc[mi][nt][2], c3 = acc[mi][nt][3];
            ps_lo += c0 * asv[nt * 2] + c1 * asv[nt * 2 + 1];
            pd_lo += c0 * adv[nt * 2] + c1 * adv[nt * 2 + 1];
            ps_hi += c2 * asv[nt * 2] + c3 * asv[nt * 2 + 1];
            pd_hi += c2 * adv[nt * 2] + c3 * adv[nt * 2 + 1];
            int col = ncol + nt * 8 + tig * 2;
            if (ok_lo) *(__half2*)&g_hh[r_lo * 128 + col] = __floats2half2_rn(c0, c1);
            if (ok_hi) *(__half2*)&g_hh[r_hi * 128 + col] = __floats2half2_rn(c2, c3);
        }
        #pragma unroll
        for (int off = 1; off < 4; off <<= 1) {
            ps_lo += __shfl_xor_sync(0xffffffffu, ps_lo, off);
            pd_lo += __shfl_xor_sync(0xffffffffu, pd_lo, off);
            ps_hi += __shfl_xor_sync(0xffffffffu, ps_hi, off);
            pd_hi += __shfl_xor_sync(0xffffffffu, pd_hi, off);
        }
        if (tig == 0) {
            if (ok_lo) { g_as[r_lo * 2 + wn] = ps_lo; g_ad[r_lo * 2 + wn] = pd_lo; }
            if (ok_hi) { g_as[r_hi * 2 + wn] = ps_hi; g_ad[r_hi * 2 + wn] = pd_hi; }
        }
    }
}

// ---------------- one-pass softmax aggregation ------------------------------
// w = exp(leaky(logit)) accumulated un-normalized (logits bounded, fp32 safe).
// Non-FINAL stores layer output pre-split bf16 (hi/lo) for the next GEMM.
template <bool FINAL>
__global__ void agg_kernel(const float* __restrict__ bias,
                           const float* __restrict__ Wr,
                           const float* __restrict__ br_ptr,
                           float* __restrict__ out, int n) {
    int d = (blockIdx.x * blockDim.x + threadIdx.x) >> 5;
    int lane = threadIdx.x & 31;
    if (d >= n) return;

    int rs = g_rowptr[d];
    int re = rs + g_deg[d];
    int head = lane >> 4;
    int f = lane * 4;

    float adh = g_ad[d * 2 + head];
    float w_self = __expf(leaky(g_as[d * 2 + head] + adh));

    float p = w_self;
    float4 acc;
    {
        uint2 u = *(const uint2*)&g_hh[d * 128 + f];
        float2 lo = __half22float2(*(__half2*)&u.x);
        float2 hi = __half22float2(*(__half2*)&u.y);
        acc.x = w_self * lo.x; acc.y = w_self * lo.y;
        acc.z = w_self * hi.x; acc.w = w_self * hi.y;
    }

    int i = rs;
    for (; i + 4 <= re; i += 4) {
        int s0 = g_csrc[i], s1 = g_csrc[i + 1], s2 = g_csrc[i + 2], s3 = g_csrc[i + 3];
        float a0 = g_as[s0 * 2 + head];
        float a1 = g_as[s1 * 2 + head];
        float a2 = g_as[s2 * 2 + head];
        float a3 = g_as[s3 * 2 + head];
        uint2 u0 = *(const uint2*)&g_hh[s0 * 128 + f];
        uint2 u1 = *(const uint2*)&g_hh[s1 * 128 + f];
        uint2 u2 = *(const uint2*)&g_hh[s2 * 128 + f];
        uint2 u3 = *(const uint2*)&g_hh[s3 * 128 + f];
        float w0 = __expf(leaky(a0 + adh));
        float w1 = __expf(leaky(a1 + adh));
        float w2 = __expf(leaky(a2 + adh));
        float w3 = __expf(leaky(a3 + adh));
        p += (w0 + w1) + (w2 + w3);
        float2 l0 = __half22float2(*(__half2*)&u0.x), h0 = __half22float2(*(__half2*)&u0.y);
        float2 l1 = __half22float2(*(__half2*)&u1.x), h1 = __half22float2(*(__half2*)&u1.y);
        float2 l2 = __half22float2(*(__half2*)&u2.x), h2 = __half22float2(*(__half2*)&u2.y);
        float2 l3 = __half22float2(*(__half2*)&u3.x), h3 = __half22float2(*(__half2*)&u3.y);
        acc.x += w0 * l0.x + w1 * l1.x + w2 * l2.x + w3 * l3.x;
        acc.y += w0 * l0.y + w1 * l1.y + w2 * l2.y + w3 * l3.y;
        acc.z += w0 * h0.x + w1 * h1.x + w2 * h2.x + w3 * h3.x;
        acc.w += w0 * h0.y + w1 * h1.y + w2 * h2.y + w3 * h3.y;
    }
    for (; i < re; i++) {
        int s = g_csrc[i];
        float a_s = g_as[s * 2 + head];
        uint2 u = *(const uint2*)&g_hh[s * 128 + f];
        float w = __expf(leaky(a_s + adh));
        p += w;
        float2 lo = __half22float2(*(__half2*)&u.x);
        float2 hi = __half22float2(*(__half2*)&u.y);
        acc.x += w * lo.x; acc.y += w * lo.y;
        acc.z += w * hi.x; acc.w += w * hi.y;
    }

    float rh = __fdividef(1.f, p);
    float4 bv = *(const float4*)&bias[f];
    float o0 = elu(acc.x * rh + bv.x);
    float o1 = elu(acc.y * rh + bv.y);
    float o2 = elu(acc.z * rh + bv.z);
    float o3 = elu(acc.w * rh + bv.w);

    if (!FINAL) {
        __nv_bfloat16 h0, l0, h1, l1, h2, l2, h3, l3;
        split_bf16(o0, h0, l0); split_bf16(o1, h1, l1);
        split_bf16(o2, h2, l2); split_bf16(o3, h3, l3);
        uint2 uh, ul;
        __nv_bfloat162 th0(h0, h1), th1(h2, h3), tl0(l0, l1), tl1(l2, l3);
        uh.x = *(unsigned*)&th0; uh.y = *(unsigned*)&th1;
        ul.x = *(unsigned*)&tl0; ul.y = *(unsigned*)&tl1;
        *(uint2*)&g_hph[d * 128 + f] = uh;
        *(uint2*)&g_hpl[d * 128 + f] = ul;
    } else {
        float4 wv = *(const float4*)&Wr[f];
        float pr = o0 * wv.x + o1 * wv.y + o2 * wv.z + o3 * wv.w;
        #pragma unroll
        for (int off = 16; off; off >>= 1)
            pr += __shfl_xor_sync(0xffffffffu, pr, off);
        if (lane == 0) out[d] = pr + br_ptr[0];
    }
}

// ---------------- launch (single stream; graph-capture safe) ----------------
extern "C" void kernel_launch(void* const* d_in, const int* in_sizes, int n_in,
                              void* d_out, int out_size) {
    const float* x      = (const float*)d_in[0];
    const int*   eidx   = (const int*)  d_in[1];
    const float* W1     = (const float*)d_in[2];
    const float* a_src1 = (const float*)d_in[3];
    const float* a_dst1 = (const float*)d_in[4];
    const float* b1     = (const float*)d_in[5];
    const float* W2     = (const float*)d_in[6];
    const float* a_src2 = (const float*)d_in[7];
    const float* a_dst2 = (const float*)d_in[8];
    const float* b2     = (const float*)d_in[9];
    const float* Wr     = (const float*)d_in[10];
    const float* br     = (const float*)d_in[11];
    float* out = (float*)d_out;

    const int* src = eidx;
    const int* dst = eidx + EE;

    int gemm_blocks = (NN + 127) / 128;
    int warp_blocks = (NN + 7) / 8;
    int e4 = EE / 4;
    int n4 = NN / 4;
    int wtot = FIN * FOUT + FOUT * FOUT;     // 32768

    wsplit_kernel<<<(wtot + 255) / 256, 256>>>(W1, W2);          // 0
    init_kernel<<<(n4 + 255) / 256, 256>>>(n4);                  // 1
    count_kernel<<<(e4 + 255) / 256, 256>>>(dst, e4);            // 2
    gemm_alpha_kernel<true><<<gemm_blocks, 256>>>(x, a_src1, a_dst1, NN); // 3 (profiled)
    scan_assign_kernel<<<NB_SCAN, 1024>>>(NN);                   // 4
    fill_kernel<<<(e4 + 255) / 256, 256>>>(src, dst, e4);        // 5

    agg_kernel<false><<<warp_blocks, 256>>>(b1, nullptr, nullptr, nullptr, NN); // 6
    gemm_alpha_kernel<false><<<gemm_blocks, 256>>>(nullptr, a_src2, a_dst2, NN); // 7
    agg_kernel<true><<<warp_blocks, 256>>>(b2, Wr, br, out, NN);                 // 8
}